// round 8
// baseline (speedup 1.0000x reference)
#include <cuda_runtime.h>
#include <cuda_bf16.h>
#include <cstdint>

static constexpr int NTOK = 2048;
static constexpr int DIM  = 512;
static constexpr int NH   = 8;

// ---------------- scratch (allocation-free: __device__ globals) ----------------
__device__ __align__(128) __nv_bfloat16 g_bimg[(size_t)NTOK * DIM];
__device__ __align__(128) __nv_bfloat16 g_bmet[(size_t)NTOK * DIM];
__device__ __align__(128) __nv_bfloat16 g_wqm [(size_t)NH * DIM * DIM];
__device__ __align__(128) __nv_bfloat16 g_wki [(size_t)NH * DIM * DIM];
__device__ __align__(128) __nv_bfloat16 g_wvi [(size_t)NH * DIM * DIM];
__device__ __align__(128) __nv_bfloat16 g_wqi [(size_t)NH * DIM * DIM];
__device__ __align__(128) __nv_bfloat16 g_wkm [(size_t)NH * DIM * DIM];
__device__ __align__(128) __nv_bfloat16 g_wvm [(size_t)NH * DIM * DIM];
__device__ __align__(128) __nv_bfloat16 g_wli [(size_t)DIM * NH * DIM];
__device__ __align__(128) __nv_bfloat16 g_wlm [(size_t)DIM * NH * DIM];
__device__ __align__(128) __nv_bfloat16 g_qm  [(size_t)NH * NTOK * DIM];
__device__ __align__(128) __nv_bfloat16 g_ki  [(size_t)NH * NTOK * DIM];
__device__ __align__(128) __nv_bfloat16 g_vit [(size_t)NH * DIM * NTOK];      // V_i^T
__device__ __align__(128) __nv_bfloat16 g_qi  [(size_t)NH * NTOK * DIM];
__device__ __align__(128) __nv_bfloat16 g_km  [(size_t)NH * NTOK * DIM];
__device__ __align__(128) __nv_bfloat16 g_vmt [(size_t)NH * DIM * NTOK];      // V_m^T
__device__ __align__(128) float         g_si  [(size_t)NH * NTOK * NTOK];
__device__ __align__(128) float         g_sm  [(size_t)NH * NTOK * NTOK];
__device__ __align__(128) __nv_bfloat16 g_pi  [(size_t)NH * NTOK * NTOK];
__device__ __align__(128) __nv_bfloat16 g_pm  [(size_t)NH * NTOK * NTOK];
__device__ __align__(128) __nv_bfloat16 g_ci  [(size_t)NTOK * NH * DIM];
__device__ __align__(128) __nv_bfloat16 g_cm  [(size_t)NTOK * NH * DIM];

#define DEVINL __device__ __forceinline__

DEVINL uint32_t s2u(const void* p) { return (uint32_t)__cvta_generic_to_shared(p); }

DEVINL void ldsm4(uint32_t* r, uint32_t a) {
    asm volatile("ldmatrix.sync.aligned.m8n8.x4.shared.b16 {%0,%1,%2,%3}, [%4];"
        : "=r"(r[0]), "=r"(r[1]), "=r"(r[2]), "=r"(r[3]) : "r"(a));
}
DEVINL void mma16(float* c, const uint32_t* a, uint32_t b0, uint32_t b1) {
    asm volatile("mma.sync.aligned.m16n8k16.row.col.f32.bf16.bf16.f32 "
        "{%0,%1,%2,%3},{%4,%5,%6,%7},{%8,%9},{%0,%1,%2,%3};"
        : "+f"(c[0]), "+f"(c[1]), "+f"(c[2]), "+f"(c[3])
        : "r"(a[0]), "r"(a[1]), "r"(a[2]), "r"(a[3]), "r"(b0), "r"(b1));
}
DEVINL uint32_t pk2(float lo, float hi) {
    __nv_bfloat162 t = __floats2bfloat162_rn(lo, hi);
    return *reinterpret_cast<uint32_t*>(&t);
}
DEVINL void cp16(uint32_t dst, const void* src) {
    asm volatile("cp.async.cg.shared.global [%0], [%1], 16;" :: "r"(dst), "l"(src));
}
#define CP_COMMIT() asm volatile("cp.async.commit_group;")
#define CP_WAIT(n)  asm volatile("cp.async.wait_group %0;" :: "n"(n))

static constexpr int RP   = 40;   // smem tile row pitch (bf16): 32 data + 8 pad
static constexpr int RPB  = 80;   // bytes
static constexpr int SP   = 132;  // epilogue stage pitch (floats) — mult of 4 (R5 lesson)
static constexpr int NS   = 4;    // cp.async pipeline stages
static constexpr int TILE_B  = 128 * RPB;            // 10240 B per tile
static constexpr int STAGE_B = 2 * TILE_B;           // A+B per stage
static constexpr int SMEM_DYN = NS * STAGE_B;        // 81920 B

// ---------------------------------------------------------------------------
// bf16 mma GEMM (NT):  C[m,n] = sum_k A[m,k] * B[n,k]  (+bias[n]) (+resid)
//   outMode: 0 = fp32 out, 1 = bf16 out, 2 = bf16 out transposed C[n][m].
// CTA 128x128, 128 thr (4 warps 2x2), warp tile 64x64, K-chunk 32, 4-stage cp.async.
// ---------------------------------------------------------------------------
__global__ __launch_bounds__(128, 2) void gemm_bf(
    const __nv_bfloat16* __restrict__ A, const __nv_bfloat16* __restrict__ B,
    void* __restrict__ Cv,
    const float* __restrict__ bias, const float* __restrict__ resid,
    int K, int lda, int ldb, int ldc, int ldr, int outMode,
    size_t strA, size_t strB, size_t strC, size_t strBias)
{
    extern __shared__ __align__(128) char dsm[];
    const uint32_t sbase = s2u(dsm);

    const int tid  = threadIdx.x;
    const int warp = tid >> 5, lane = tid & 31;
    const int wm = warp & 1, wn = warp >> 1;       // 2x2 warp grid
    const int gid = lane >> 2, tig = lane & 3;
    const int z  = blockIdx.z;
    const int m0 = blockIdx.y * 128, n0 = blockIdx.x * 128;

    A += (size_t)z * strA;
    B += (size_t)z * strB;
    char* Cp8 = (char*)Cv + (size_t)z * strC * (outMode == 0 ? 4 : 2);
    if (bias) bias += (size_t)z * strBias;

    // fill mapping: each thread owns one 128-row's 64B (4 x 16B cp.async)
    const __nv_bfloat16* Ap = A + (size_t)(m0 + tid) * lda;
    const __nv_bfloat16* Bp = B + (size_t)(n0 + tid) * ldb;
    const uint32_t sa_t = sbase + tid * RPB;
    const uint32_t sb_t = sa_t + TILE_B;

    const int NC = K / 32;

    auto issue = [&](int c) {
        const uint32_t so = (uint32_t)((c & (NS - 1)) * STAGE_B);
        const __nv_bfloat16* ga = Ap + c * 32;
        const __nv_bfloat16* gb = Bp + c * 32;
#pragma unroll
        for (int u = 0; u < 4; u++) {
            cp16(sa_t + so + u * 16, ga + u * 8);
            cp16(sb_t + so + u * 16, gb + u * 8);
        }
    };

    float acc[4][8][4];
#pragma unroll
    for (int i = 0; i < 4; i++)
#pragma unroll
        for (int j = 0; j < 8; j++)
#pragma unroll
            for (int r = 0; r < 4; r++) acc[i][j][r] = 0.0f;

    // ldmatrix per-lane byte offsets
    const int lrow8  = (lane & 7) + ((lane >> 3) & 1) * 8;
    const int lchunk = (lane >> 4) * 16;
    uint32_t aoff[4], boff[4];
#pragma unroll
    for (int mt = 0; mt < 4; mt++) aoff[mt] = (uint32_t)((wm * 64 + mt * 16 + lrow8) * RPB + lchunk);
#pragma unroll
    for (int np = 0; np < 4; np++) boff[np] = (uint32_t)((wn * 64 + np * 16 + lrow8) * RPB + lchunk);

    // prologue
#pragma unroll
    for (int c = 0; c < NS - 1; c++) {
        if (c < NC) issue(c);
        CP_COMMIT();
    }

    for (int c = 0; c < NC; c++) {
        CP_WAIT(NS - 2);
        __syncthreads();
        if (c + NS - 1 < NC) issue(c + NS - 1);
        CP_COMMIT();

        const uint32_t so = (uint32_t)((c & (NS - 1)) * STAGE_B);
        const uint32_t ab = sbase + so;
        const uint32_t bb = ab + TILE_B;
#pragma unroll
        for (int ks = 0; ks < 2; ks++) {
            uint32_t a[4][4], b[4][4];
#pragma unroll
            for (int mt = 0; mt < 4; mt++) ldsm4(a[mt], ab + aoff[mt] + ks * 32);
#pragma unroll
            for (int np = 0; np < 4; np++) ldsm4(b[np], bb + boff[np] + ks * 32);
#pragma unroll
            for (int mt = 0; mt < 4; mt++)
#pragma unroll
                for (int np = 0; np < 4; np++) {
                    mma16(acc[mt][2 * np],     a[mt], b[np][0], b[np][2]);
                    mma16(acc[mt][2 * np + 1], a[mt], b[np][1], b[np][3]);
                }
        }
    }
    CP_WAIT(0);
    __syncthreads();

    // -------- epilogue: stage 64 m-rows at a time through smem --------
    float* stage = (float*)dsm;
    for (int p = 0; p < 2; p++) {
        if (wm == p) {
#pragma unroll
            for (int mt = 0; mt < 4; mt++) {
                const int lr = mt * 16 + gid;
#pragma unroll
                for (int nt = 0; nt < 8; nt++) {
                    const int col = wn * 64 + nt * 8 + 2 * tig;
                    *(float2*)&stage[lr * SP + col]       = make_float2(acc[mt][nt][0], acc[mt][nt][1]);
                    *(float2*)&stage[(lr + 8) * SP + col] = make_float2(acc[mt][nt][2], acc[mt][nt][3]);
                }
            }
        }
        __syncthreads();

        if (outMode == 0) {
            float* C = (float*)Cp8;
#pragma unroll
            for (int i = 0; i < 16; i++) {
                const int idx = tid + i * 128;
                const int row = idx >> 5;
                const int c4  = (idx & 31) * 4;
                float4 v = *(float4*)&stage[row * SP + c4];
                const int n = n0 + c4;
                if (bias) { v.x += bias[n]; v.y += bias[n + 1]; v.z += bias[n + 2]; v.w += bias[n + 3]; }
                const int m = m0 + p * 64 + row;
                if (resid) {
                    float4 rr = *(const float4*)(resid + (size_t)m * ldr + n);
                    v.x += rr.x; v.y += rr.y; v.z += rr.z; v.w += rr.w;
                }
                *(float4*)(C + (size_t)m * ldc + n) = v;
            }
        } else if (outMode == 1) {
            __nv_bfloat16* C = (__nv_bfloat16*)Cp8;
#pragma unroll
            for (int i = 0; i < 16; i++) {
                const int idx = tid + i * 128;
                const int row = idx >> 5;
                const int c4  = (idx & 31) * 4;
                float4 v = *(float4*)&stage[row * SP + c4];
                const int n = n0 + c4;
                if (bias) { v.x += bias[n]; v.y += bias[n + 1]; v.z += bias[n + 2]; v.w += bias[n + 3]; }
                uint2 o = make_uint2(pk2(v.x, v.y), pk2(v.z, v.w));
                *(uint2*)(C + (size_t)(m0 + p * 64 + row) * ldc + n) = o;
            }
        } else {
            __nv_bfloat16* C = (__nv_bfloat16*)Cp8;
#pragma unroll
            for (int i = 0; i < 16; i++) {
                const int idx = tid + i * 128;
                const int mq  = (idx & 15) * 4;
                const int col = idx >> 4;
                const float bv = bias ? bias[n0 + col] : 0.0f;
                float f0 = stage[(mq + 0) * SP + col] + bv;
                float f1 = stage[(mq + 1) * SP + col] + bv;
                float f2 = stage[(mq + 2) * SP + col] + bv;
                float f3 = stage[(mq + 3) * SP + col] + bv;
                uint2 o = make_uint2(pk2(f0, f1), pk2(f2, f3));
                *(uint2*)(C + (size_t)(n0 + col) * ldc + m0 + p * 64 + mq) = o;
            }
        }
        __syncthreads();
    }
}

// ---------------------------------------------------------------------------
// fp32 -> bf16 bulk convert, 10 tensors in one launch (grid.y = tensor idx)
// ---------------------------------------------------------------------------
struct CvtJobs { const float* s[10]; __nv_bfloat16* d[10]; int n[10]; };

__global__ __launch_bounds__(256) void cvt_bf(CvtJobs j)
{
    const int t = blockIdx.y;
    const float* src = j.s[t];
    __nv_bfloat16* dst = j.d[t];
    const int n = j.n[t];
    const int stride = gridDim.x * blockDim.x * 4;
    for (int i = (blockIdx.x * blockDim.x + threadIdx.x) * 4; i < n; i += stride) {
        float4 v = *(const float4*)(src + i);
        uint2 o = make_uint2(pk2(v.x, v.y), pk2(v.z, v.w));
        *(uint2*)(dst + i) = o;
    }
}

// ---------------------------------------------------------------------------
// Row softmax (2048 cols): fp32 in -> bf16 probs out, one block per row.
// ---------------------------------------------------------------------------
__global__ __launch_bounds__(256) void softmax_bf(
    const float* __restrict__ S, __nv_bfloat16* __restrict__ P, float scale)
{
    const float* row = S + (size_t)blockIdx.x * NTOK;
    __nv_bfloat16* prow = P + (size_t)blockIdx.x * NTOK;
    const int tid = threadIdx.x;

    float4 u0 = *(const float4*)(row + tid * 8);
    float4 u1 = *(const float4*)(row + tid * 8 + 4);
    float v[8] = {u0.x, u0.y, u0.z, u0.w, u1.x, u1.y, u1.z, u1.w};

    float mx = -1e30f;
#pragma unroll
    for (int i = 0; i < 8; i++) { v[i] *= scale; mx = fmaxf(mx, v[i]); }

    __shared__ float red[8];
#pragma unroll
    for (int o = 16; o; o >>= 1) mx = fmaxf(mx, __shfl_xor_sync(0xffffffffu, mx, o));
    if ((tid & 31) == 0) red[tid >> 5] = mx;
    __syncthreads();
    mx = red[0];
#pragma unroll
    for (int i = 1; i < 8; i++) mx = fmaxf(mx, red[i]);

    float sum = 0.0f;
#pragma unroll
    for (int i = 0; i < 8; i++) { v[i] = __expf(v[i] - mx); sum += v[i]; }
    __syncthreads();
#pragma unroll
    for (int o = 16; o; o >>= 1) sum += __shfl_xor_sync(0xffffffffu, sum, o);
    if ((tid & 31) == 0) red[tid >> 5] = sum;
    __syncthreads();
    sum = red[0];
#pragma unroll
    for (int i = 1; i < 8; i++) sum += red[i];

    const float inv = 1.0f / sum;
    uint4 o = make_uint4(pk2(v[0] * inv, v[1] * inv), pk2(v[2] * inv, v[3] * inv),
                         pk2(v[4] * inv, v[5] * inv), pk2(v[6] * inv, v[7] * inv));
    *(uint4*)(prow + tid * 8) = o;
}

// ---------------------------------------------------------------------------
extern "C" void kernel_launch(void* const* d_in, const int* in_sizes, int n_in,
                              void* d_out, int out_size)
{
    (void)in_sizes; (void)n_in; (void)out_size;

    const float* image = (const float*)d_in[0];
    const float* meta  = (const float*)d_in[1];
    const float* Wq_m  = (const float*)d_in[2];  const float* bq_m = (const float*)d_in[3];
    const float* Wk_i  = (const float*)d_in[4];  const float* bk_i = (const float*)d_in[5];
    const float* Wv_i  = (const float*)d_in[6];  const float* bv_i = (const float*)d_in[7];
    const float* Wq_i  = (const float*)d_in[8];  const float* bq_i = (const float*)d_in[9];
    const float* Wk_m  = (const float*)d_in[10]; const float* bk_m = (const float*)d_in[11];
    const float* Wv_m  = (const float*)d_in[12]; const float* bv_m = (const float*)d_in[13];
    const float* Wli   = (const float*)d_in[14]; const float* bli  = (const float*)d_in[15];
    const float* Wlm   = (const float*)d_in[16]; const float* blm  = (const float*)d_in[17];
    float* out = (float*)d_out;

    __nv_bfloat16 *bimg, *bmet, *wqm, *wki, *wvi, *wqi, *wkm, *wvm, *wli, *wlm;
    __nv_bfloat16 *qm, *ki, *vit, *qi, *km, *vmt, *pi, *pm, *ci, *cm;
    float *si, *sm;
    cudaGetSymbolAddress((void**)&bimg, g_bimg);
    cudaGetSymbolAddress((void**)&bmet, g_bmet);
    cudaGetSymbolAddress((void**)&wqm,  g_wqm);
    cudaGetSymbolAddress((void**)&wki,  g_wki);
    cudaGetSymbolAddress((void**)&wvi,  g_wvi);
    cudaGetSymbolAddress((void**)&wqi,  g_wqi);
    cudaGetSymbolAddress((void**)&wkm,  g_wkm);
    cudaGetSymbolAddress((void**)&wvm,  g_wvm);
    cudaGetSymbolAddress((void**)&wli,  g_wli);
    cudaGetSymbolAddress((void**)&wlm,  g_wlm);
    cudaGetSymbolAddress((void**)&qm,   g_qm);
    cudaGetSymbolAddress((void**)&ki,   g_ki);
    cudaGetSymbolAddress((void**)&vit,  g_vit);
    cudaGetSymbolAddress((void**)&qi,   g_qi);
    cudaGetSymbolAddress((void**)&km,   g_km);
    cudaGetSymbolAddress((void**)&vmt,  g_vmt);
    cudaGetSymbolAddress((void**)&si,   g_si);
    cudaGetSymbolAddress((void**)&sm,   g_sm);
    cudaGetSymbolAddress((void**)&pi,   g_pi);
    cudaGetSymbolAddress((void**)&pm,   g_pm);
    cudaGetSymbolAddress((void**)&ci,   g_ci);
    cudaGetSymbolAddress((void**)&cm,   g_cm);

    cudaFuncSetAttribute(gemm_bf, cudaFuncAttributeMaxDynamicSharedMemorySize, SMEM_DYN);

    // ---- pre-convert all fp32 operands to bf16 (one launch)
    {
        CvtJobs j;
        const int nW = NH * DIM * DIM;
        const int nL = DIM * NH * DIM;
        const int nX = NTOK * DIM;
        j.s[0] = image; j.d[0] = bimg; j.n[0] = nX;
        j.s[1] = meta;  j.d[1] = bmet; j.n[1] = nX;
        j.s[2] = Wq_m;  j.d[2] = wqm;  j.n[2] = nW;
        j.s[3] = Wk_i;  j.d[3] = wki;  j.n[3] = nW;
        j.s[4] = Wv_i;  j.d[4] = wvi;  j.n[4] = nW;
        j.s[5] = Wq_i;  j.d[5] = wqi;  j.n[5] = nW;
        j.s[6] = Wk_m;  j.d[6] = wkm;  j.n[6] = nW;
        j.s[7] = Wv_m;  j.d[7] = wvm;  j.n[7] = nW;
        j.s[8] = Wli;   j.d[8] = wli;  j.n[8] = nL;
        j.s[9] = Wlm;   j.d[9] = wlm;  j.n[9] = nL;
        cvt_bf<<<dim3(1024, 10), 256>>>(j);
    }

    const dim3 blk(128);
    const size_t sW = (size_t)DIM * DIM;
    const size_t sO = (size_t)NTOK * DIM;
    const size_t sS = (size_t)NTOK * NTOK;

    // ---- projections (bf16): X @ W[h]^T + b[h]
    const dim3 gproj(DIM / 128, NTOK / 128, NH);
    gemm_bf<<<gproj, blk, SMEM_DYN>>>(bmet, wqm, qm,  bq_m, nullptr, DIM, DIM, DIM, DIM,  0, 1, 0, sW, sO, DIM);
    gemm_bf<<<gproj, blk, SMEM_DYN>>>(bimg, wki, ki,  bk_i, nullptr, DIM, DIM, DIM, DIM,  0, 1, 0, sW, sO, DIM);
    gemm_bf<<<gproj, blk, SMEM_DYN>>>(bimg, wvi, vit, bv_i, nullptr, DIM, DIM, DIM, NTOK, 0, 2, 0, sW, sO, DIM);
    gemm_bf<<<gproj, blk, SMEM_DYN>>>(bimg, wqi, qi,  bq_i, nullptr, DIM, DIM, DIM, DIM,  0, 1, 0, sW, sO, DIM);
    gemm_bf<<<gproj, blk, SMEM_DYN>>>(bmet, wkm, km,  bk_m, nullptr, DIM, DIM, DIM, DIM,  0, 1, 0, sW, sO, DIM);
    gemm_bf<<<gproj, blk, SMEM_DYN>>>(bmet, wvm, vmt, bv_m, nullptr, DIM, DIM, DIM, NTOK, 0, 2, 0, sW, sO, DIM);

    // ---- scores: Q[h] @ K[h]^T -> fp32
    const dim3 gsc(NTOK / 128, NTOK / 128, NH);
    gemm_bf<<<gsc, blk, SMEM_DYN>>>(qm, ki, si, nullptr, nullptr, DIM, DIM, DIM, NTOK, 0, 0, sO, sO, sS, 0);
    gemm_bf<<<gsc, blk, SMEM_DYN>>>(qi, km, sm, nullptr, nullptr, DIM, DIM, DIM, NTOK, 0, 0, sO, sO, sS, 0);

    // ---- softmax (fp32 -> bf16), scale = 1/sqrt(512)
    const float scale = 0.04419417382415922f;
    softmax_bf<<<NH * NTOK, 256>>>(si, pi, scale);
    softmax_bf<<<NH * NTOK, 256>>>(sm, pm, scale);

    // ---- AV: P[h] @ (V^T[h])^T -> concat [2048, H*512] bf16
    const dim3 gav(DIM / 128, NTOK / 128, NH);
    gemm_bf<<<gav, blk, SMEM_DYN>>>(pi, vit, ci, nullptr, nullptr, NTOK, NTOK, NTOK, NH * DIM, 0, 1, sS, sO, (size_t)DIM, 0);
    gemm_bf<<<gav, blk, SMEM_DYN>>>(pm, vmt, cm, nullptr, nullptr, NTOK, NTOK, NTOK, NH * DIM, 0, 1, sS, sO, (size_t)DIM, 0);

    // ---- final linears + bias + residual(fp32) into d_out [2048, 1024]
    const dim3 gfin(DIM / 128, NTOK / 128, 1);
    gemm_bf<<<gfin, blk, SMEM_DYN>>>(ci, wli, out,       bli, image, NH * DIM, NH * DIM, NH * DIM, 2 * DIM, DIM, 0, 0, 0, 0, 0);
    gemm_bf<<<gfin, blk, SMEM_DYN>>>(cm, wlm, out + DIM, blm, meta,  NH * DIM, NH * DIM, NH * DIM, 2 * DIM, DIM, 0, 0, 0, 0, 0);
}

// round 9
// speedup vs baseline: 1.0572x; 1.0572x over previous
#include <cuda_runtime.h>
#include <cuda_bf16.h>
#include <cstdint>

static constexpr int NTOK = 2048;
static constexpr int DIM  = 512;
static constexpr int NH   = 8;

// ---------------- scratch (allocation-free: __device__ globals) ----------------
__device__ __align__(128) __nv_bfloat16 g_bimg[(size_t)NTOK * DIM];
__device__ __align__(128) __nv_bfloat16 g_bmet[(size_t)NTOK * DIM];
__device__ __align__(128) __nv_bfloat16 g_wqm [(size_t)NH * DIM * DIM];
__device__ __align__(128) __nv_bfloat16 g_wki [(size_t)NH * DIM * DIM];
__device__ __align__(128) __nv_bfloat16 g_wvi [(size_t)NH * DIM * DIM];
__device__ __align__(128) __nv_bfloat16 g_wqi [(size_t)NH * DIM * DIM];
__device__ __align__(128) __nv_bfloat16 g_wkm [(size_t)NH * DIM * DIM];
__device__ __align__(128) __nv_bfloat16 g_wvm [(size_t)NH * DIM * DIM];
__device__ __align__(128) __nv_bfloat16 g_wli [(size_t)DIM * NH * DIM];
__device__ __align__(128) __nv_bfloat16 g_wlm [(size_t)DIM * NH * DIM];
__device__ __align__(128) __nv_bfloat16 g_qm  [(size_t)NH * NTOK * DIM];
__device__ __align__(128) __nv_bfloat16 g_ki  [(size_t)NH * NTOK * DIM];
__device__ __align__(128) __nv_bfloat16 g_vit [(size_t)NH * DIM * NTOK];      // V_i^T
__device__ __align__(128) __nv_bfloat16 g_qi  [(size_t)NH * NTOK * DIM];
__device__ __align__(128) __nv_bfloat16 g_km  [(size_t)NH * NTOK * DIM];
__device__ __align__(128) __nv_bfloat16 g_vmt [(size_t)NH * DIM * NTOK];      // V_m^T
__device__ __align__(128) float         g_si  [(size_t)NH * NTOK * NTOK];
__device__ __align__(128) float         g_sm  [(size_t)NH * NTOK * NTOK];
__device__ __align__(128) __nv_bfloat16 g_pi  [(size_t)NH * NTOK * NTOK];
__device__ __align__(128) __nv_bfloat16 g_pm  [(size_t)NH * NTOK * NTOK];
__device__ __align__(128) __nv_bfloat16 g_ci  [(size_t)NTOK * NH * DIM];
__device__ __align__(128) __nv_bfloat16 g_cm  [(size_t)NTOK * NH * DIM];

#define DEVINL __device__ __forceinline__

DEVINL uint32_t s2u(const void* p) { return (uint32_t)__cvta_generic_to_shared(p); }

DEVINL void ldsm4(uint32_t* r, uint32_t a) {
    asm volatile("ldmatrix.sync.aligned.m8n8.x4.shared.b16 {%0,%1,%2,%3}, [%4];"
        : "=r"(r[0]), "=r"(r[1]), "=r"(r[2]), "=r"(r[3]) : "r"(a));
}
DEVINL void mma16(float* c, const uint32_t* a, uint32_t b0, uint32_t b1) {
    asm volatile("mma.sync.aligned.m16n8k16.row.col.f32.bf16.bf16.f32 "
        "{%0,%1,%2,%3},{%4,%5,%6,%7},{%8,%9},{%0,%1,%2,%3};"
        : "+f"(c[0]), "+f"(c[1]), "+f"(c[2]), "+f"(c[3])
        : "r"(a[0]), "r"(a[1]), "r"(a[2]), "r"(a[3]), "r"(b0), "r"(b1));
}
DEVINL uint32_t pk2(float lo, float hi) {
    __nv_bfloat162 t = __floats2bfloat162_rn(lo, hi);
    return *reinterpret_cast<uint32_t*>(&t);
}
DEVINL void cp16(uint32_t dst, const void* src) {
    asm volatile("cp.async.cg.shared.global [%0], [%1], 16;" :: "r"(dst), "l"(src));
}
#define CP_COMMIT() asm volatile("cp.async.commit_group;")
#define CP_WAIT(n)  asm volatile("cp.async.wait_group %0;" :: "n"(n))

static constexpr int RP   = 40;   // smem tile row pitch (bf16): 32 data + 8 pad
static constexpr int RPB  = 80;   // bytes
static constexpr int SP   = 132;  // epilogue stage pitch (floats) — mult of 4 (R5 lesson)
static constexpr int NS   = 4;    // cp.async pipeline stages
static constexpr int TILE_B  = 128 * RPB;            // 10240 B per tile
static constexpr int STAGE_B = 2 * TILE_B;           // A+B per stage
static constexpr int SMEM_DYN = NS * STAGE_B;        // 81920 B

// ---------------------------------------------------------------------------
// bf16 mma GEMM (NT):  C[m,n] = sum_k A[m,k] * B[n,k]  (+bias[n]) (+resid)
//   outMode: 0 = fp32 out, 1 = bf16 out, 2 = bf16 out transposed C[n][m].
// CTA 128x128, 256 thr (8 warps 2x4), warp tile 64x32, K-chunk 32,
// 4-stage cp.async, hoisted double-buffered fragments (all 12 ldsm before mma).
// ---------------------------------------------------------------------------
__global__ __launch_bounds__(256, 2) void gemm_bf(
    const __nv_bfloat16* __restrict__ A, const __nv_bfloat16* __restrict__ B,
    void* __restrict__ Cv,
    const float* __restrict__ bias, const float* __restrict__ resid,
    int K, int lda, int ldb, int ldc, int ldr, int outMode,
    size_t strA, size_t strB, size_t strC, size_t strBias)
{
    extern __shared__ __align__(128) char dsm[];
    const uint32_t sbase = s2u(dsm);

    const int tid  = threadIdx.x;
    const int warp = tid >> 5, lane = tid & 31;
    const int wm = warp & 1, wn = warp >> 1;
    const int gid = lane >> 2, tig = lane & 3;
    const int z  = blockIdx.z;
    const int m0 = blockIdx.y * 128, n0 = blockIdx.x * 128;

    A += (size_t)z * strA;
    B += (size_t)z * strB;
    char* Cp8 = (char*)Cv + (size_t)z * strC * (outMode == 0 ? 4 : 2);
    if (bias) bias += (size_t)z * strBias;

    // fill mapping: row = tid&127; up = (tid>>7)*2 -> 16B units {up, up+1}
    const int frow = tid & 127;
    const int fup  = (tid >> 7) * 2;
    const __nv_bfloat16* Ap = A + (size_t)(m0 + frow) * lda + fup * 8;
    const __nv_bfloat16* Bp = B + (size_t)(n0 + frow) * ldb + fup * 8;
    const uint32_t sa_t = sbase + frow * RPB + fup * 16;
    const uint32_t sb_t = sa_t + TILE_B;

    const int NC = K / 32;

    auto issue = [&](int c) {
        const uint32_t so = (uint32_t)((c & (NS - 1)) * STAGE_B);
        const __nv_bfloat16* ga = Ap + c * 32;
        const __nv_bfloat16* gb = Bp + c * 32;
        cp16(sa_t + so,      ga);
        cp16(sa_t + so + 16, ga + 8);
        cp16(sb_t + so,      gb);
        cp16(sb_t + so + 16, gb + 8);
    };

    float acc[4][4][4];
#pragma unroll
    for (int i = 0; i < 4; i++)
#pragma unroll
        for (int j = 0; j < 4; j++)
#pragma unroll
            for (int r = 0; r < 4; r++) acc[i][j][r] = 0.0f;

    // ldmatrix per-lane byte offsets
    const int lrow8  = (lane & 7) + ((lane >> 3) & 1) * 8;
    const int lchunk = (lane >> 4) * 16;
    uint32_t aoff[4], boff[2];
#pragma unroll
    for (int mt = 0; mt < 4; mt++) aoff[mt] = (uint32_t)((wm * 64 + mt * 16 + lrow8) * RPB + lchunk);
#pragma unroll
    for (int np = 0; np < 2; np++) boff[np] = (uint32_t)((wn * 32 + np * 16 + lrow8) * RPB + lchunk);

    // prologue
#pragma unroll
    for (int c = 0; c < NS - 1; c++) {
        if (c < NC) issue(c);
        CP_COMMIT();
    }

    for (int c = 0; c < NC; c++) {
        CP_WAIT(NS - 2);
        __syncthreads();
        if (c + NS - 1 < NC) issue(c + NS - 1);
        CP_COMMIT();

        const uint32_t so = (uint32_t)((c & (NS - 1)) * STAGE_B);
        const uint32_t ab = sbase + so;
        const uint32_t bb = ab + TILE_B;

        // hoist ALL fragment loads for both ks halves, then run all 32 mma
        uint32_t a[2][4][4], b[2][2][4];
#pragma unroll
        for (int ks = 0; ks < 2; ks++) {
#pragma unroll
            for (int mt = 0; mt < 4; mt++) ldsm4(a[ks][mt], ab + aoff[mt] + ks * 32);
#pragma unroll
            for (int np = 0; np < 2; np++) ldsm4(b[ks][np], bb + boff[np] + ks * 32);
        }
#pragma unroll
        for (int ks = 0; ks < 2; ks++)
#pragma unroll
            for (int mt = 0; mt < 4; mt++)
#pragma unroll
                for (int np = 0; np < 2; np++) {
                    mma16(acc[mt][2 * np],     a[ks][mt], b[ks][np][0], b[ks][np][2]);
                    mma16(acc[mt][2 * np + 1], a[ks][mt], b[ks][np][1], b[ks][np][3]);
                }
    }
    CP_WAIT(0);
    __syncthreads();

    // -------- epilogue: stage 64 m-rows at a time through smem --------
    float* stage = (float*)dsm;
    for (int p = 0; p < 2; p++) {
        if (wm == p) {
#pragma unroll
            for (int mt = 0; mt < 4; mt++) {
                const int lr = mt * 16 + gid;
#pragma unroll
                for (int nt = 0; nt < 4; nt++) {
                    const int col = wn * 32 + nt * 8 + 2 * tig;
                    *(float2*)&stage[lr * SP + col]       = make_float2(acc[mt][nt][0], acc[mt][nt][1]);
                    *(float2*)&stage[(lr + 8) * SP + col] = make_float2(acc[mt][nt][2], acc[mt][nt][3]);
                }
            }
        }
        __syncthreads();

        if (outMode == 0) {
            float* C = (float*)Cp8;
#pragma unroll
            for (int i = 0; i < 8; i++) {
                const int idx = tid + i * 256;
                const int row = idx >> 5;
                const int c4  = (idx & 31) * 4;
                float4 v = *(float4*)&stage[row * SP + c4];
                const int n = n0 + c4;
                if (bias) { v.x += bias[n]; v.y += bias[n + 1]; v.z += bias[n + 2]; v.w += bias[n + 3]; }
                const int m = m0 + p * 64 + row;
                if (resid) {
                    float4 rr = *(const float4*)(resid + (size_t)m * ldr + n);
                    v.x += rr.x; v.y += rr.y; v.z += rr.z; v.w += rr.w;
                }
                *(float4*)(C + (size_t)m * ldc + n) = v;
            }
        } else if (outMode == 1) {
            __nv_bfloat16* C = (__nv_bfloat16*)Cp8;
#pragma unroll
            for (int i = 0; i < 8; i++) {
                const int idx = tid + i * 256;
                const int row = idx >> 5;
                const int c4  = (idx & 31) * 4;
                float4 v = *(float4*)&stage[row * SP + c4];
                const int n = n0 + c4;
                if (bias) { v.x += bias[n]; v.y += bias[n + 1]; v.z += bias[n + 2]; v.w += bias[n + 3]; }
                uint2 o = make_uint2(pk2(v.x, v.y), pk2(v.z, v.w));
                *(uint2*)(C + (size_t)(m0 + p * 64 + row) * ldc + n) = o;
            }
        } else {
            __nv_bfloat16* C = (__nv_bfloat16*)Cp8;
#pragma unroll
            for (int i = 0; i < 8; i++) {
                const int idx = tid + i * 256;
                const int mq  = (idx & 15) * 4;
                const int col = idx >> 4;
                const float bv = bias ? bias[n0 + col] : 0.0f;
                float f0 = stage[(mq + 0) * SP + col] + bv;
                float f1 = stage[(mq + 1) * SP + col] + bv;
                float f2 = stage[(mq + 2) * SP + col] + bv;
                float f3 = stage[(mq + 3) * SP + col] + bv;
                uint2 o = make_uint2(pk2(f0, f1), pk2(f2, f3));
                *(uint2*)(C + (size_t)(n0 + col) * ldc + m0 + p * 64 + mq) = o;
            }
        }
        __syncthreads();
    }
}

// ---------------------------------------------------------------------------
// fp32 -> bf16 bulk convert, 10 tensors in one launch (grid.y = tensor idx)
// ---------------------------------------------------------------------------
struct CvtJobs { const float* s[10]; __nv_bfloat16* d[10]; int n[10]; };

__global__ __launch_bounds__(256) void cvt_bf(CvtJobs j)
{
    const int t = blockIdx.y;
    const float* src = j.s[t];
    __nv_bfloat16* dst = j.d[t];
    const int n = j.n[t];
    const int stride = gridDim.x * blockDim.x * 4;
    for (int i = (blockIdx.x * blockDim.x + threadIdx.x) * 4; i < n; i += stride) {
        float4 v = *(const float4*)(src + i);
        uint2 o = make_uint2(pk2(v.x, v.y), pk2(v.z, v.w));
        *(uint2*)(dst + i) = o;
    }
}

// ---------------------------------------------------------------------------
// Row softmax (2048 cols): fp32 in -> bf16 probs out, one block per row.
// ---------------------------------------------------------------------------
__global__ __launch_bounds__(256) void softmax_bf(
    const float* __restrict__ S, __nv_bfloat16* __restrict__ P, float scale)
{
    const float* row = S + (size_t)blockIdx.x * NTOK;
    __nv_bfloat16* prow = P + (size_t)blockIdx.x * NTOK;
    const int tid = threadIdx.x;

    float4 u0 = *(const float4*)(row + tid * 8);
    float4 u1 = *(const float4*)(row + tid * 8 + 4);
    float v[8] = {u0.x, u0.y, u0.z, u0.w, u1.x, u1.y, u1.z, u1.w};

    float mx = -1e30f;
#pragma unroll
    for (int i = 0; i < 8; i++) { v[i] *= scale; mx = fmaxf(mx, v[i]); }

    __shared__ float red[8];
#pragma unroll
    for (int o = 16; o; o >>= 1) mx = fmaxf(mx, __shfl_xor_sync(0xffffffffu, mx, o));
    if ((tid & 31) == 0) red[tid >> 5] = mx;
    __syncthreads();
    mx = red[0];
#pragma unroll
    for (int i = 1; i < 8; i++) mx = fmaxf(mx, red[i]);

    float sum = 0.0f;
#pragma unroll
    for (int i = 0; i < 8; i++) { v[i] = __expf(v[i] - mx); sum += v[i]; }
    __syncthreads();
#pragma unroll
    for (int o = 16; o; o >>= 1) sum += __shfl_xor_sync(0xffffffffu, sum, o);
    if ((tid & 31) == 0) red[tid >> 5] = sum;
    __syncthreads();
    sum = red[0];
#pragma unroll
    for (int i = 1; i < 8; i++) sum += red[i];

    const float inv = 1.0f / sum;
    uint4 o = make_uint4(pk2(v[0] * inv, v[1] * inv), pk2(v[2] * inv, v[3] * inv),
                         pk2(v[4] * inv, v[5] * inv), pk2(v[6] * inv, v[7] * inv));
    *(uint4*)(prow + tid * 8) = o;
}

// ---------------------------------------------------------------------------
extern "C" void kernel_launch(void* const* d_in, const int* in_sizes, int n_in,
                              void* d_out, int out_size)
{
    (void)in_sizes; (void)n_in; (void)out_size;

    const float* image = (const float*)d_in[0];
    const float* meta  = (const float*)d_in[1];
    const float* Wq_m  = (const float*)d_in[2];  const float* bq_m = (const float*)d_in[3];
    const float* Wk_i  = (const float*)d_in[4];  const float* bk_i = (const float*)d_in[5];
    const float* Wv_i  = (const float*)d_in[6];  const float* bv_i = (const float*)d_in[7];
    const float* Wq_i  = (const float*)d_in[8];  const float* bq_i = (const float*)d_in[9];
    const float* Wk_m  = (const float*)d_in[10]; const float* bk_m = (const float*)d_in[11];
    const float* Wv_m  = (const float*)d_in[12]; const float* bv_m = (const float*)d_in[13];
    const float* Wli   = (const float*)d_in[14]; const float* bli  = (const float*)d_in[15];
    const float* Wlm   = (const float*)d_in[16]; const float* blm  = (const float*)d_in[17];
    float* out = (float*)d_out;

    __nv_bfloat16 *bimg, *bmet, *wqm, *wki, *wvi, *wqi, *wkm, *wvm, *wli, *wlm;
    __nv_bfloat16 *qm, *ki, *vit, *qi, *km, *vmt, *pi, *pm, *ci, *cm;
    float *si, *sm;
    cudaGetSymbolAddress((void**)&bimg, g_bimg);
    cudaGetSymbolAddress((void**)&bmet, g_bmet);
    cudaGetSymbolAddress((void**)&wqm,  g_wqm);
    cudaGetSymbolAddress((void**)&wki,  g_wki);
    cudaGetSymbolAddress((void**)&wvi,  g_wvi);
    cudaGetSymbolAddress((void**)&wqi,  g_wqi);
    cudaGetSymbolAddress((void**)&wkm,  g_wkm);
    cudaGetSymbolAddress((void**)&wvm,  g_wvm);
    cudaGetSymbolAddress((void**)&wli,  g_wli);
    cudaGetSymbolAddress((void**)&wlm,  g_wlm);
    cudaGetSymbolAddress((void**)&qm,   g_qm);
    cudaGetSymbolAddress((void**)&ki,   g_ki);
    cudaGetSymbolAddress((void**)&vit,  g_vit);
    cudaGetSymbolAddress((void**)&qi,   g_qi);
    cudaGetSymbolAddress((void**)&km,   g_km);
    cudaGetSymbolAddress((void**)&vmt,  g_vmt);
    cudaGetSymbolAddress((void**)&si,   g_si);
    cudaGetSymbolAddress((void**)&sm,   g_sm);
    cudaGetSymbolAddress((void**)&pi,   g_pi);
    cudaGetSymbolAddress((void**)&pm,   g_pm);
    cudaGetSymbolAddress((void**)&ci,   g_ci);
    cudaGetSymbolAddress((void**)&cm,   g_cm);

    cudaFuncSetAttribute(gemm_bf, cudaFuncAttributeMaxDynamicSharedMemorySize, SMEM_DYN);

    // ---- pre-convert all fp32 operands to bf16 (one launch)
    {
        CvtJobs j;
        const int nW = NH * DIM * DIM;
        const int nL = DIM * NH * DIM;
        const int nX = NTOK * DIM;
        j.s[0] = image; j.d[0] = bimg; j.n[0] = nX;
        j.s[1] = meta;  j.d[1] = bmet; j.n[1] = nX;
        j.s[2] = Wq_m;  j.d[2] = wqm;  j.n[2] = nW;
        j.s[3] = Wk_i;  j.d[3] = wki;  j.n[3] = nW;
        j.s[4] = Wv_i;  j.d[4] = wvi;  j.n[4] = nW;
        j.s[5] = Wq_i;  j.d[5] = wqi;  j.n[5] = nW;
        j.s[6] = Wk_m;  j.d[6] = wkm;  j.n[6] = nW;
        j.s[7] = Wv_m;  j.d[7] = wvm;  j.n[7] = nW;
        j.s[8] = Wli;   j.d[8] = wli;  j.n[8] = nL;
        j.s[9] = Wlm;   j.d[9] = wlm;  j.n[9] = nL;
        cvt_bf<<<dim3(1024, 10), 256>>>(j);
    }

    const dim3 blk(256);
    const size_t sW = (size_t)DIM * DIM;
    const size_t sO = (size_t)NTOK * DIM;
    const size_t sS = (size_t)NTOK * NTOK;

    // ---- projections (bf16): X @ W[h]^T + b[h]
    const dim3 gproj(DIM / 128, NTOK / 128, NH);
    gemm_bf<<<gproj, blk, SMEM_DYN>>>(bmet, wqm, qm,  bq_m, nullptr, DIM, DIM, DIM, DIM,  0, 1, 0, sW, sO, DIM);
    gemm_bf<<<gproj, blk, SMEM_DYN>>>(bimg, wki, ki,  bk_i, nullptr, DIM, DIM, DIM, DIM,  0, 1, 0, sW, sO, DIM);
    gemm_bf<<<gproj, blk, SMEM_DYN>>>(bimg, wvi, vit, bv_i, nullptr, DIM, DIM, DIM, NTOK, 0, 2, 0, sW, sO, DIM);
    gemm_bf<<<gproj, blk, SMEM_DYN>>>(bimg, wqi, qi,  bq_i, nullptr, DIM, DIM, DIM, DIM,  0, 1, 0, sW, sO, DIM);
    gemm_bf<<<gproj, blk, SMEM_DYN>>>(bmet, wkm, km,  bk_m, nullptr, DIM, DIM, DIM, DIM,  0, 1, 0, sW, sO, DIM);
    gemm_bf<<<gproj, blk, SMEM_DYN>>>(bmet, wvm, vmt, bv_m, nullptr, DIM, DIM, DIM, NTOK, 0, 2, 0, sW, sO, DIM);

    // ---- scores: Q[h] @ K[h]^T -> fp32
    const dim3 gsc(NTOK / 128, NTOK / 128, NH);
    gemm_bf<<<gsc, blk, SMEM_DYN>>>(qm, ki, si, nullptr, nullptr, DIM, DIM, DIM, NTOK, 0, 0, sO, sO, sS, 0);
    gemm_bf<<<gsc, blk, SMEM_DYN>>>(qi, km, sm, nullptr, nullptr, DIM, DIM, DIM, NTOK, 0, 0, sO, sO, sS, 0);

    // ---- softmax (fp32 -> bf16), scale = 1/sqrt(512)
    const float scale = 0.04419417382415922f;
    softmax_bf<<<NH * NTOK, 256>>>(si, pi, scale);
    softmax_bf<<<NH * NTOK, 256>>>(sm, pm, scale);

    // ---- AV: P[h] @ (V^T[h])^T -> concat [2048, H*512] bf16
    const dim3 gav(DIM / 128, NTOK / 128, NH);
    gemm_bf<<<gav, blk, SMEM_DYN>>>(pi, vit, ci, nullptr, nullptr, NTOK, NTOK, NTOK, NH * DIM, 0, 1, sS, sO, (size_t)DIM, 0);
    gemm_bf<<<gav, blk, SMEM_DYN>>>(pm, vmt, cm, nullptr, nullptr, NTOK, NTOK, NTOK, NH * DIM, 0, 1, sS, sO, (size_t)DIM, 0);

    // ---- final linears + bias + residual(fp32) into d_out [2048, 1024]
    const dim3 gfin(DIM / 128, NTOK / 128, 1);
    gemm_bf<<<gfin, blk, SMEM_DYN>>>(ci, wli, out,       bli, image, NH * DIM, NH * DIM, NH * DIM, 2 * DIM, DIM, 0, 0, 0, 0, 0);
    gemm_bf<<<gfin, blk, SMEM_DYN>>>(cm, wlm, out + DIM, blm, meta,  NH * DIM, NH * DIM, NH * DIM, 2 * DIM, DIM, 0, 0, 0, 0, 0);
}

// round 10
// speedup vs baseline: 1.2582x; 1.1901x over previous
#include <cuda_runtime.h>
#include <cuda_bf16.h>
#include <cstdint>

static constexpr int NTOK = 2048;
static constexpr int DIM  = 512;
static constexpr int NH   = 8;

// ---------------- scratch (allocation-free: __device__ globals) ----------------
__device__ __align__(128) __nv_bfloat16 g_bimg[(size_t)NTOK * DIM];
__device__ __align__(128) __nv_bfloat16 g_bmet[(size_t)NTOK * DIM];
__device__ __align__(128) __nv_bfloat16 g_wqm [(size_t)NH * DIM * DIM];
__device__ __align__(128) __nv_bfloat16 g_wki [(size_t)NH * DIM * DIM];
__device__ __align__(128) __nv_bfloat16 g_wvi [(size_t)NH * DIM * DIM];
__device__ __align__(128) __nv_bfloat16 g_wqi [(size_t)NH * DIM * DIM];
__device__ __align__(128) __nv_bfloat16 g_wkm [(size_t)NH * DIM * DIM];
__device__ __align__(128) __nv_bfloat16 g_wvm [(size_t)NH * DIM * DIM];
__device__ __align__(128) __nv_bfloat16 g_wli [(size_t)DIM * NH * DIM];
__device__ __align__(128) __nv_bfloat16 g_wlm [(size_t)DIM * NH * DIM];
__device__ __align__(128) __nv_bfloat16 g_qm  [(size_t)NH * NTOK * DIM];
__device__ __align__(128) __nv_bfloat16 g_ki  [(size_t)NH * NTOK * DIM];
__device__ __align__(128) __nv_bfloat16 g_vit [(size_t)NH * DIM * NTOK];      // V_i^T
__device__ __align__(128) __nv_bfloat16 g_qi  [(size_t)NH * NTOK * DIM];
__device__ __align__(128) __nv_bfloat16 g_km  [(size_t)NH * NTOK * DIM];
__device__ __align__(128) __nv_bfloat16 g_vmt [(size_t)NH * DIM * NTOK];      // V_m^T
__device__ __align__(128) float         g_si  [(size_t)NH * NTOK * NTOK];
__device__ __align__(128) float         g_sm  [(size_t)NH * NTOK * NTOK];
__device__ __align__(128) __nv_bfloat16 g_pi  [(size_t)NH * NTOK * NTOK];
__device__ __align__(128) __nv_bfloat16 g_pm  [(size_t)NH * NTOK * NTOK];
__device__ __align__(128) __nv_bfloat16 g_ci  [(size_t)NTOK * NH * DIM];
__device__ __align__(128) __nv_bfloat16 g_cm  [(size_t)NTOK * NH * DIM];

#define DEVINL __device__ __forceinline__

DEVINL uint32_t s2u(const void* p) { return (uint32_t)__cvta_generic_to_shared(p); }

DEVINL void ldsm4(uint32_t* r, uint32_t a) {
    asm volatile("ldmatrix.sync.aligned.m8n8.x4.shared.b16 {%0,%1,%2,%3}, [%4];"
        : "=r"(r[0]), "=r"(r[1]), "=r"(r[2]), "=r"(r[3]) : "r"(a));
}
DEVINL void mma16(float* c, const uint32_t* a, uint32_t b0, uint32_t b1) {
    asm volatile("mma.sync.aligned.m16n8k16.row.col.f32.bf16.bf16.f32 "
        "{%0,%1,%2,%3},{%4,%5,%6,%7},{%8,%9},{%0,%1,%2,%3};"
        : "+f"(c[0]), "+f"(c[1]), "+f"(c[2]), "+f"(c[3])
        : "r"(a[0]), "r"(a[1]), "r"(a[2]), "r"(a[3]), "r"(b0), "r"(b1));
}
DEVINL uint32_t pk2(float lo, float hi) {
    __nv_bfloat162 t = __floats2bfloat162_rn(lo, hi);
    return *reinterpret_cast<uint32_t*>(&t);
}
DEVINL void cp16(uint32_t dst, const void* src) {
    asm volatile("cp.async.cg.shared.global [%0], [%1], 16;" :: "r"(dst), "l"(src));
}
#define CP_COMMIT() asm volatile("cp.async.commit_group;")
#define CP_WAIT(n)  asm volatile("cp.async.wait_group %0;" :: "n"(n))

static constexpr int RP   = 40;   // smem tile row pitch (bf16): 32 data + 8 pad
static constexpr int RPB  = 80;   // bytes
static constexpr int SP   = 132;  // epilogue stage pitch (floats) — mult of 4 (R5 lesson)
static constexpr int NS   = 4;    // cp.async pipeline stages
static constexpr int TILE_B  = 128 * RPB;            // 10240 B per tile
static constexpr int STAGE_B = 2 * TILE_B;           // A+B per stage
static constexpr int SMEM_DYN = NS * STAGE_B;        // 81920 B

// --------------- per-z job descriptor (all pointers pre-offset on host) --------
struct Job {
    const __nv_bfloat16* A;
    const __nv_bfloat16* B;
    char*                C;      // base, already dtype-scaled
    const float*         bias;
    const float*         resid;
    int lda, ldb, ldc, ldr, outMode;   // outMode: 0 fp32, 1 bf16, 2 bf16 transposed
};
static constexpr int MAXJ = 48;
struct Jobs { Job j[MAXJ]; };

// ---------------------------------------------------------------------------
// bf16 mma GEMM (NT), batched by z over a job table.
// CTA 128x128, 256 thr, warp tile 64x32, K-chunk 32, 4-stage cp.async.
// ---------------------------------------------------------------------------
__global__ __launch_bounds__(256, 2) void gemm_batch(Jobs jobs, int K)
{
    extern __shared__ __align__(128) char dsm[];
    const uint32_t sbase = s2u(dsm);
    const Job J = jobs.j[blockIdx.z];

    const int tid  = threadIdx.x;
    const int warp = tid >> 5, lane = tid & 31;
    const int wm = warp & 1, wn = warp >> 1;
    const int gid = lane >> 2, tig = lane & 3;
    const int m0 = blockIdx.y * 128, n0 = blockIdx.x * 128;

    // fill mapping: row = tid&127; up = (tid>>7)*2 -> 16B units {up, up+1}
    const int frow = tid & 127;
    const int fup  = (tid >> 7) * 2;
    const __nv_bfloat16* Ap = J.A + (size_t)(m0 + frow) * J.lda + fup * 8;
    const __nv_bfloat16* Bp = J.B + (size_t)(n0 + frow) * J.ldb + fup * 8;
    const uint32_t sa_t = sbase + frow * RPB + fup * 16;
    const uint32_t sb_t = sa_t + TILE_B;

    const int NC = K / 32;

    auto issue = [&](int c) {
        const uint32_t so = (uint32_t)((c & (NS - 1)) * STAGE_B);
        const __nv_bfloat16* ga = Ap + c * 32;
        const __nv_bfloat16* gb = Bp + c * 32;
        cp16(sa_t + so,      ga);
        cp16(sa_t + so + 16, ga + 8);
        cp16(sb_t + so,      gb);
        cp16(sb_t + so + 16, gb + 8);
    };

    float acc[4][4][4];
#pragma unroll
    for (int i = 0; i < 4; i++)
#pragma unroll
        for (int j = 0; j < 4; j++)
#pragma unroll
            for (int r = 0; r < 4; r++) acc[i][j][r] = 0.0f;

    // ldmatrix per-lane byte offsets
    const int lrow8  = (lane & 7) + ((lane >> 3) & 1) * 8;
    const int lchunk = (lane >> 4) * 16;
    uint32_t aoff[4], boff[2];
#pragma unroll
    for (int mt = 0; mt < 4; mt++) aoff[mt] = (uint32_t)((wm * 64 + mt * 16 + lrow8) * RPB + lchunk);
#pragma unroll
    for (int np = 0; np < 2; np++) boff[np] = (uint32_t)((wn * 32 + np * 16 + lrow8) * RPB + lchunk);

    // prologue
#pragma unroll
    for (int c = 0; c < NS - 1; c++) {
        if (c < NC) issue(c);
        CP_COMMIT();
    }

    for (int c = 0; c < NC; c++) {
        CP_WAIT(NS - 2);
        __syncthreads();
        if (c + NS - 1 < NC) issue(c + NS - 1);
        CP_COMMIT();

        const uint32_t so = (uint32_t)((c & (NS - 1)) * STAGE_B);
        const uint32_t ab = sbase + so;
        const uint32_t bb = ab + TILE_B;
#pragma unroll
        for (int ks = 0; ks < 2; ks++) {
            uint32_t a[4][4], b[2][4];
#pragma unroll
            for (int mt = 0; mt < 4; mt++) ldsm4(a[mt], ab + aoff[mt] + ks * 32);
#pragma unroll
            for (int np = 0; np < 2; np++) ldsm4(b[np], bb + boff[np] + ks * 32);
#pragma unroll
            for (int mt = 0; mt < 4; mt++)
#pragma unroll
                for (int np = 0; np < 2; np++) {
                    mma16(acc[mt][2 * np],     a[mt], b[np][0], b[np][2]);
                    mma16(acc[mt][2 * np + 1], a[mt], b[np][1], b[np][3]);
                }
        }
    }
    CP_WAIT(0);
    __syncthreads();

    // -------- epilogue: stage 64 m-rows at a time through smem --------
    float* stage = (float*)dsm;
    for (int p = 0; p < 2; p++) {
        if (wm == p) {
#pragma unroll
            for (int mt = 0; mt < 4; mt++) {
                const int lr = mt * 16 + gid;
#pragma unroll
                for (int nt = 0; nt < 4; nt++) {
                    const int col = wn * 32 + nt * 8 + 2 * tig;
                    *(float2*)&stage[lr * SP + col]       = make_float2(acc[mt][nt][0], acc[mt][nt][1]);
                    *(float2*)&stage[(lr + 8) * SP + col] = make_float2(acc[mt][nt][2], acc[mt][nt][3]);
                }
            }
        }
        __syncthreads();

        if (J.outMode == 0) {
            float* C = (float*)J.C;
#pragma unroll
            for (int i = 0; i < 8; i++) {
                const int idx = tid + i * 256;
                const int row = idx >> 5;
                const int c4  = (idx & 31) * 4;
                float4 v = *(float4*)&stage[row * SP + c4];
                const int n = n0 + c4;
                if (J.bias) { v.x += J.bias[n]; v.y += J.bias[n + 1]; v.z += J.bias[n + 2]; v.w += J.bias[n + 3]; }
                const int m = m0 + p * 64 + row;
                if (J.resid) {
                    float4 rr = *(const float4*)(J.resid + (size_t)m * J.ldr + n);
                    v.x += rr.x; v.y += rr.y; v.z += rr.z; v.w += rr.w;
                }
                *(float4*)(C + (size_t)m * J.ldc + n) = v;
            }
        } else if (J.outMode == 1) {
            __nv_bfloat16* C = (__nv_bfloat16*)J.C;
#pragma unroll
            for (int i = 0; i < 8; i++) {
                const int idx = tid + i * 256;
                const int row = idx >> 5;
                const int c4  = (idx & 31) * 4;
                float4 v = *(float4*)&stage[row * SP + c4];
                const int n = n0 + c4;
                if (J.bias) { v.x += J.bias[n]; v.y += J.bias[n + 1]; v.z += J.bias[n + 2]; v.w += J.bias[n + 3]; }
                uint2 o = make_uint2(pk2(v.x, v.y), pk2(v.z, v.w));
                *(uint2*)(C + (size_t)(m0 + p * 64 + row) * J.ldc + n) = o;
            }
        } else {
            __nv_bfloat16* C = (__nv_bfloat16*)J.C;
#pragma unroll
            for (int i = 0; i < 8; i++) {
                const int idx = tid + i * 256;
                const int mq  = (idx & 15) * 4;
                const int col = idx >> 4;
                const float bv = J.bias ? J.bias[n0 + col] : 0.0f;
                float f0 = stage[(mq + 0) * SP + col] + bv;
                float f1 = stage[(mq + 1) * SP + col] + bv;
                float f2 = stage[(mq + 2) * SP + col] + bv;
                float f3 = stage[(mq + 3) * SP + col] + bv;
                uint2 o = make_uint2(pk2(f0, f1), pk2(f2, f3));
                *(uint2*)(C + (size_t)(n0 + col) * J.ldc + m0 + p * 64 + mq) = o;
            }
        }
        __syncthreads();
    }
}

// ---------------------------------------------------------------------------
// fp32 -> bf16 bulk convert, 10 tensors in one launch (grid.y = tensor idx)
// ---------------------------------------------------------------------------
struct CvtJobs { const float* s[10]; __nv_bfloat16* d[10]; int n[10]; };

__global__ __launch_bounds__(256) void cvt_bf(CvtJobs j)
{
    const int t = blockIdx.y;
    const float* src = j.s[t];
    __nv_bfloat16* dst = j.d[t];
    const int n = j.n[t];
    const int stride = gridDim.x * blockDim.x * 4;
    for (int i = (blockIdx.x * blockDim.x + threadIdx.x) * 4; i < n; i += stride) {
        float4 v = *(const float4*)(src + i);
        uint2 o = make_uint2(pk2(v.x, v.y), pk2(v.z, v.w));
        *(uint2*)(dst + i) = o;
    }
}

// ---------------------------------------------------------------------------
// Row softmax (2048 cols): fp32 in -> bf16 out; grid.y selects tensor pair.
// ---------------------------------------------------------------------------
__global__ __launch_bounds__(256) void softmax_bf(
    const float* __restrict__ S0, __nv_bfloat16* __restrict__ P0,
    const float* __restrict__ S1, __nv_bfloat16* __restrict__ P1, float scale)
{
    const float* S = blockIdx.y ? S1 : S0;
    __nv_bfloat16* P = blockIdx.y ? P1 : P0;
    const float* row = S + (size_t)blockIdx.x * NTOK;
    __nv_bfloat16* prow = P + (size_t)blockIdx.x * NTOK;
    const int tid = threadIdx.x;

    float4 u0 = *(const float4*)(row + tid * 8);
    float4 u1 = *(const float4*)(row + tid * 8 + 4);
    float v[8] = {u0.x, u0.y, u0.z, u0.w, u1.x, u1.y, u1.z, u1.w};

    float mx = -1e30f;
#pragma unroll
    for (int i = 0; i < 8; i++) { v[i] *= scale; mx = fmaxf(mx, v[i]); }

    __shared__ float red[8];
#pragma unroll
    for (int o = 16; o; o >>= 1) mx = fmaxf(mx, __shfl_xor_sync(0xffffffffu, mx, o));
    if ((tid & 31) == 0) red[tid >> 5] = mx;
    __syncthreads();
    mx = red[0];
#pragma unroll
    for (int i = 1; i < 8; i++) mx = fmaxf(mx, red[i]);

    float sum = 0.0f;
#pragma unroll
    for (int i = 0; i < 8; i++) { v[i] = __expf(v[i] - mx); sum += v[i]; }
    __syncthreads();
#pragma unroll
    for (int o = 16; o; o >>= 1) sum += __shfl_xor_sync(0xffffffffu, sum, o);
    if ((tid & 31) == 0) red[tid >> 5] = sum;
    __syncthreads();
    sum = red[0];
#pragma unroll
    for (int i = 1; i < 8; i++) sum += red[i];

    const float inv = 1.0f / sum;
    uint4 o = make_uint4(pk2(v[0] * inv, v[1] * inv), pk2(v[2] * inv, v[3] * inv),
                         pk2(v[4] * inv, v[5] * inv), pk2(v[6] * inv, v[7] * inv));
    *(uint4*)(prow + tid * 8) = o;
}

// ---------------------------------------------------------------------------
extern "C" void kernel_launch(void* const* d_in, const int* in_sizes, int n_in,
                              void* d_out, int out_size)
{
    (void)in_sizes; (void)n_in; (void)out_size;

    const float* image = (const float*)d_in[0];
    const float* meta  = (const float*)d_in[1];
    const float* Wq_m  = (const float*)d_in[2];  const float* bq_m = (const float*)d_in[3];
    const float* Wk_i  = (const float*)d_in[4];  const float* bk_i = (const float*)d_in[5];
    const float* Wv_i  = (const float*)d_in[6];  const float* bv_i = (const float*)d_in[7];
    const float* Wq_i  = (const float*)d_in[8];  const float* bq_i = (const float*)d_in[9];
    const float* Wk_m  = (const float*)d_in[10]; const float* bk_m = (const float*)d_in[11];
    const float* Wv_m  = (const float*)d_in[12]; const float* bv_m = (const float*)d_in[13];
    const float* Wli   = (const float*)d_in[14]; const float* bli  = (const float*)d_in[15];
    const float* Wlm   = (const float*)d_in[16]; const float* blm  = (const float*)d_in[17];
    float* out = (float*)d_out;

    __nv_bfloat16 *bimg, *bmet, *wqm, *wki, *wvi, *wqi, *wkm, *wvm, *wli, *wlm;
    __nv_bfloat16 *qm, *ki, *vit, *qi, *km, *vmt, *pi, *pm, *ci, *cm;
    float *si, *sm;
    cudaGetSymbolAddress((void**)&bimg, g_bimg);
    cudaGetSymbolAddress((void**)&bmet, g_bmet);
    cudaGetSymbolAddress((void**)&wqm,  g_wqm);
    cudaGetSymbolAddress((void**)&wki,  g_wki);
    cudaGetSymbolAddress((void**)&wvi,  g_wvi);
    cudaGetSymbolAddress((void**)&wqi,  g_wqi);
    cudaGetSymbolAddress((void**)&wkm,  g_wkm);
    cudaGetSymbolAddress((void**)&wvm,  g_wvm);
    cudaGetSymbolAddress((void**)&wli,  g_wli);
    cudaGetSymbolAddress((void**)&wlm,  g_wlm);
    cudaGetSymbolAddress((void**)&qm,   g_qm);
    cudaGetSymbolAddress((void**)&ki,   g_ki);
    cudaGetSymbolAddress((void**)&vit,  g_vit);
    cudaGetSymbolAddress((void**)&qi,   g_qi);
    cudaGetSymbolAddress((void**)&km,   g_km);
    cudaGetSymbolAddress((void**)&vmt,  g_vmt);
    cudaGetSymbolAddress((void**)&si,   g_si);
    cudaGetSymbolAddress((void**)&sm,   g_sm);
    cudaGetSymbolAddress((void**)&pi,   g_pi);
    cudaGetSymbolAddress((void**)&pm,   g_pm);
    cudaGetSymbolAddress((void**)&ci,   g_ci);
    cudaGetSymbolAddress((void**)&cm,   g_cm);

    cudaFuncSetAttribute(gemm_batch, cudaFuncAttributeMaxDynamicSharedMemorySize, SMEM_DYN);

    // ---- pre-convert all fp32 operands to bf16 (one launch)
    {
        CvtJobs j;
        const int nW = NH * DIM * DIM;
        const int nL = DIM * NH * DIM;
        const int nX = NTOK * DIM;
        j.s[0] = image; j.d[0] = bimg; j.n[0] = nX;
        j.s[1] = meta;  j.d[1] = bmet; j.n[1] = nX;
        j.s[2] = Wq_m;  j.d[2] = wqm;  j.n[2] = nW;
        j.s[3] = Wk_i;  j.d[3] = wki;  j.n[3] = nW;
        j.s[4] = Wv_i;  j.d[4] = wvi;  j.n[4] = nW;
        j.s[5] = Wq_i;  j.d[5] = wqi;  j.n[5] = nW;
        j.s[6] = Wk_m;  j.d[6] = wkm;  j.n[6] = nW;
        j.s[7] = Wv_m;  j.d[7] = wvm;  j.n[7] = nW;
        j.s[8] = Wli;   j.d[8] = wli;  j.n[8] = nL;
        j.s[9] = Wlm;   j.d[9] = wlm;  j.n[9] = nL;
        cvt_bf<<<dim3(1024, 10), 256>>>(j);
    }

    const dim3 blk(256);
    const size_t sW  = (size_t)DIM * DIM;
    const size_t sO  = (size_t)NTOK * DIM;
    const size_t sOT = (size_t)DIM * NTOK;
    const size_t sS  = (size_t)NTOK * NTOK;

    // ---- projections: ONE launch, 48 jobs (6 gemms x 8 heads)
    {
        Jobs jb;
        const __nv_bfloat16* As[6]  = {bmet, bimg, bimg, bimg, bmet, bmet};
        const __nv_bfloat16* Ws[6]  = {wqm,  wki,  wvi,  wqi,  wkm,  wvm};
        __nv_bfloat16*       Cs[6]  = {qm,   ki,   vit,  qi,   km,   vmt};
        const float*         Bs[6]  = {bq_m, bk_i, bv_i, bq_i, bk_m, bv_m};
        const int            md[6]  = {1, 1, 2, 1, 1, 2};
        for (int g = 0; g < 6; g++)
            for (int h = 0; h < NH; h++) {
                Job& J = jb.j[g * NH + h];
                J.A = As[g];
                J.B = Ws[g] + (size_t)h * sW;
                J.C = (char*)(Cs[g] + (md[g] == 2 ? (size_t)h * sOT : (size_t)h * sO));
                J.bias = Bs[g] + (size_t)h * DIM;
                J.resid = nullptr;
                J.lda = DIM; J.ldb = DIM;
                J.ldc = (md[g] == 2) ? NTOK : DIM;
                J.ldr = 0; J.outMode = md[g];
            }
        gemm_batch<<<dim3(DIM / 128, NTOK / 128, 48), blk, SMEM_DYN>>>(jb, DIM);
    }

    // ---- scores: ONE launch, 16 jobs (2 directions x 8 heads), fp32 out
    {
        Jobs jb;
        for (int p = 0; p < 2; p++)
            for (int h = 0; h < NH; h++) {
                Job& J = jb.j[p * NH + h];
                J.A = (p ? qi : qm) + (size_t)h * sO;
                J.B = (p ? km : ki) + (size_t)h * sO;
                J.C = (char*)((p ? sm : si) + (size_t)h * sS);
                J.bias = nullptr; J.resid = nullptr;
                J.lda = DIM; J.ldb = DIM; J.ldc = NTOK; J.ldr = 0; J.outMode = 0;
            }
        gemm_batch<<<dim3(NTOK / 128, NTOK / 128, 16), blk, SMEM_DYN>>>(jb, DIM);
    }

    // ---- softmax (both directions, one launch), scale = 1/sqrt(512)
    softmax_bf<<<dim3(NH * NTOK, 2), 256>>>(si, pi, sm, pm, 0.04419417382415922f);

    // ---- AV: ONE launch, 16 jobs -> concat [2048, 4096] bf16
    {
        Jobs jb;
        for (int p = 0; p < 2; p++)
            for (int h = 0; h < NH; h++) {
                Job& J = jb.j[p * NH + h];
                J.A = (p ? pm : pi) + (size_t)h * sS;
                J.B = (p ? vmt : vit) + (size_t)h * sOT;
                J.C = (char*)((p ? cm : ci) + (size_t)h * DIM);
                J.bias = nullptr; J.resid = nullptr;
                J.lda = NTOK; J.ldb = NTOK; J.ldc = NH * DIM; J.ldr = 0; J.outMode = 1;
            }
        gemm_batch<<<dim3(DIM / 128, NTOK / 128, 16), blk, SMEM_DYN>>>(jb, NTOK);
    }

    // ---- final linears: ONE launch, 2 jobs, bias + fp32 residual -> d_out
    {
        Jobs jb;
        jb.j[0] = { ci, wli, (char*)out,          bli, image, NH * DIM, NH * DIM, 2 * DIM, DIM, 0 };
        jb.j[1] = { cm, wlm, (char*)(out + DIM),  blm, meta,  NH * DIM, NH * DIM, 2 * DIM, DIM, 0 };
        gemm_batch<<<dim3(DIM / 128, NTOK / 128, 2), blk, SMEM_DYN>>>(jb, NH * DIM);
    }
}

// round 11
// speedup vs baseline: 1.2803x; 1.0176x over previous
#include <cuda_runtime.h>
#include <cuda_bf16.h>
#include <cstdint>

static constexpr int NTOK = 2048;
static constexpr int DIM  = 512;
static constexpr int NH   = 8;

// ---------------- scratch (allocation-free: __device__ globals) ----------------
__device__ __align__(128) __nv_bfloat16 g_bimg[(size_t)NTOK * DIM];
__device__ __align__(128) __nv_bfloat16 g_bmet[(size_t)NTOK * DIM];
__device__ __align__(128) __nv_bfloat16 g_wqm [(size_t)NH * DIM * DIM];
__device__ __align__(128) __nv_bfloat16 g_wki [(size_t)NH * DIM * DIM];
__device__ __align__(128) __nv_bfloat16 g_wvi [(size_t)NH * DIM * DIM];
__device__ __align__(128) __nv_bfloat16 g_wqi [(size_t)NH * DIM * DIM];
__device__ __align__(128) __nv_bfloat16 g_wkm [(size_t)NH * DIM * DIM];
__device__ __align__(128) __nv_bfloat16 g_wvm [(size_t)NH * DIM * DIM];
__device__ __align__(128) __nv_bfloat16 g_wli [(size_t)DIM * NH * DIM];
__device__ __align__(128) __nv_bfloat16 g_wlm [(size_t)DIM * NH * DIM];
__device__ __align__(128) __nv_bfloat16 g_qm  [(size_t)NH * NTOK * DIM];
__device__ __align__(128) __nv_bfloat16 g_ki  [(size_t)NH * NTOK * DIM];
__device__ __align__(128) __nv_bfloat16 g_vit [(size_t)NH * DIM * NTOK];      // V_i^T
__device__ __align__(128) __nv_bfloat16 g_qi  [(size_t)NH * NTOK * DIM];
__device__ __align__(128) __nv_bfloat16 g_km  [(size_t)NH * NTOK * DIM];
__device__ __align__(128) __nv_bfloat16 g_vmt [(size_t)NH * DIM * NTOK];      // V_m^T
__device__ __align__(128) __nv_bfloat16 g_si  [(size_t)NH * NTOK * NTOK];     // scaled scores bf16
__device__ __align__(128) __nv_bfloat16 g_sm  [(size_t)NH * NTOK * NTOK];
__device__ __align__(128) __nv_bfloat16 g_pi  [(size_t)NH * NTOK * NTOK];     // softmax probs bf16
__device__ __align__(128) __nv_bfloat16 g_pm  [(size_t)NH * NTOK * NTOK];
__device__ __align__(128) __nv_bfloat16 g_ci  [(size_t)NTOK * NH * DIM];
__device__ __align__(128) __nv_bfloat16 g_cm  [(size_t)NTOK * NH * DIM];

#define DEVINL __device__ __forceinline__

DEVINL uint32_t s2u(const void* p) { return (uint32_t)__cvta_generic_to_shared(p); }

DEVINL void ldsm4(uint32_t* r, uint32_t a) {
    asm volatile("ldmatrix.sync.aligned.m8n8.x4.shared.b16 {%0,%1,%2,%3}, [%4];"
        : "=r"(r[0]), "=r"(r[1]), "=r"(r[2]), "=r"(r[3]) : "r"(a));
}
DEVINL void mma16(float* c, const uint32_t* a, uint32_t b0, uint32_t b1) {
    asm volatile("mma.sync.aligned.m16n8k16.row.col.f32.bf16.bf16.f32 "
        "{%0,%1,%2,%3},{%4,%5,%6,%7},{%8,%9},{%0,%1,%2,%3};"
        : "+f"(c[0]), "+f"(c[1]), "+f"(c[2]), "+f"(c[3])
        : "r"(a[0]), "r"(a[1]), "r"(a[2]), "r"(a[3]), "r"(b0), "r"(b1));
}
DEVINL uint32_t pk2(float lo, float hi) {
    __nv_bfloat162 t = __floats2bfloat162_rn(lo, hi);
    return *reinterpret_cast<uint32_t*>(&t);
}
DEVINL void cp16(uint32_t dst, const void* src) {
    asm volatile("cp.async.cg.shared.global [%0], [%1], 16;" :: "r"(dst), "l"(src));
}
#define CP_COMMIT() asm volatile("cp.async.commit_group;")
#define CP_WAIT(n)  asm volatile("cp.async.wait_group %0;" :: "n"(n))

static constexpr int RP   = 40;   // smem tile row pitch (bf16): 32 data + 8 pad
static constexpr int RPB  = 80;   // bytes
static constexpr int SP   = 132;  // epilogue stage pitch (floats) — mult of 4 (R5 lesson)
static constexpr int NS   = 4;    // cp.async pipeline stages
static constexpr int TILE_B  = 128 * RPB;            // 10240 B per tile
static constexpr int STAGE_B = 2 * TILE_B;           // A+B per stage
static constexpr int SMEM_DYN = NS * STAGE_B;        // 81920 B

// --------------- per-z job descriptor (all pointers pre-offset on host) --------
struct Job {
    const __nv_bfloat16* A;
    const __nv_bfloat16* B;
    char*                C;
    const float*         bias;
    const float*         resid;
    float scale;                       // multiplies accumulator before bias
    int lda, ldb, ldc, ldr, outMode;   // outMode: 0 fp32, 1 bf16, 2 bf16 transposed
};
static constexpr int MAXJ = 48;
struct Jobs { Job j[MAXJ]; };

// ---------------------------------------------------------------------------
// bf16 mma GEMM (NT), batched by z over a job table.
// CTA 128x128, 256 thr, warp tile 64x32, K-chunk 32, 4-stage cp.async.
// ---------------------------------------------------------------------------
__global__ __launch_bounds__(256, 2) void gemm_batch(Jobs jobs, int K)
{
    extern __shared__ __align__(128) char dsm[];
    const uint32_t sbase = s2u(dsm);
    const Job J = jobs.j[blockIdx.z];

    const int tid  = threadIdx.x;
    const int warp = tid >> 5, lane = tid & 31;
    const int wm = warp & 1, wn = warp >> 1;
    const int gid = lane >> 2, tig = lane & 3;
    const int m0 = blockIdx.y * 128, n0 = blockIdx.x * 128;

    const int frow = tid & 127;
    const int fup  = (tid >> 7) * 2;
    const __nv_bfloat16* Ap = J.A + (size_t)(m0 + frow) * J.lda + fup * 8;
    const __nv_bfloat16* Bp = J.B + (size_t)(n0 + frow) * J.ldb + fup * 8;
    const uint32_t sa_t = sbase + frow * RPB + fup * 16;
    const uint32_t sb_t = sa_t + TILE_B;

    const int NC = K / 32;

    auto issue = [&](int c) {
        const uint32_t so = (uint32_t)((c & (NS - 1)) * STAGE_B);
        const __nv_bfloat16* ga = Ap + c * 32;
        const __nv_bfloat16* gb = Bp + c * 32;
        cp16(sa_t + so,      ga);
        cp16(sa_t + so + 16, ga + 8);
        cp16(sb_t + so,      gb);
        cp16(sb_t + so + 16, gb + 8);
    };

    float acc[4][4][4];
#pragma unroll
    for (int i = 0; i < 4; i++)
#pragma unroll
        for (int j = 0; j < 4; j++)
#pragma unroll
            for (int r = 0; r < 4; r++) acc[i][j][r] = 0.0f;

    const int lrow8  = (lane & 7) + ((lane >> 3) & 1) * 8;
    const int lchunk = (lane >> 4) * 16;
    uint32_t aoff[4], boff[2];
#pragma unroll
    for (int mt = 0; mt < 4; mt++) aoff[mt] = (uint32_t)((wm * 64 + mt * 16 + lrow8) * RPB + lchunk);
#pragma unroll
    for (int np = 0; np < 2; np++) boff[np] = (uint32_t)((wn * 32 + np * 16 + lrow8) * RPB + lchunk);

#pragma unroll
    for (int c = 0; c < NS - 1; c++) {
        if (c < NC) issue(c);
        CP_COMMIT();
    }

    for (int c = 0; c < NC; c++) {
        CP_WAIT(NS - 2);
        __syncthreads();
        if (c + NS - 1 < NC) issue(c + NS - 1);
        CP_COMMIT();

        const uint32_t so = (uint32_t)((c & (NS - 1)) * STAGE_B);
        const uint32_t ab = sbase + so;
        const uint32_t bb = ab + TILE_B;
#pragma unroll
        for (int ks = 0; ks < 2; ks++) {
            uint32_t a[4][4], b[2][4];
#pragma unroll
            for (int mt = 0; mt < 4; mt++) ldsm4(a[mt], ab + aoff[mt] + ks * 32);
#pragma unroll
            for (int np = 0; np < 2; np++) ldsm4(b[np], bb + boff[np] + ks * 32);
#pragma unroll
            for (int mt = 0; mt < 4; mt++)
#pragma unroll
                for (int np = 0; np < 2; np++) {
                    mma16(acc[mt][2 * np],     a[mt], b[np][0], b[np][2]);
                    mma16(acc[mt][2 * np + 1], a[mt], b[np][1], b[np][3]);
                }
        }
    }
    CP_WAIT(0);
    __syncthreads();

    // -------- epilogue: stage 64 m-rows at a time through smem --------
    float* stage = (float*)dsm;
    const float sc = J.scale;
    for (int p = 0; p < 2; p++) {
        if (wm == p) {
#pragma unroll
            for (int mt = 0; mt < 4; mt++) {
                const int lr = mt * 16 + gid;
#pragma unroll
                for (int nt = 0; nt < 4; nt++) {
                    const int col = wn * 32 + nt * 8 + 2 * tig;
                    *(float2*)&stage[lr * SP + col]       = make_float2(acc[mt][nt][0], acc[mt][nt][1]);
                    *(float2*)&stage[(lr + 8) * SP + col] = make_float2(acc[mt][nt][2], acc[mt][nt][3]);
                }
            }
        }
        __syncthreads();

        if (J.outMode == 0) {
            float* C = (float*)J.C;
#pragma unroll
            for (int i = 0; i < 8; i++) {
                const int idx = tid + i * 256;
                const int row = idx >> 5;
                const int c4  = (idx & 31) * 4;
                float4 v = *(float4*)&stage[row * SP + c4];
                v.x *= sc; v.y *= sc; v.z *= sc; v.w *= sc;
                const int n = n0 + c4;
                if (J.bias) { v.x += J.bias[n]; v.y += J.bias[n + 1]; v.z += J.bias[n + 2]; v.w += J.bias[n + 3]; }
                const int m = m0 + p * 64 + row;
                if (J.resid) {
                    float4 rr = *(const float4*)(J.resid + (size_t)m * J.ldr + n);
                    v.x += rr.x; v.y += rr.y; v.z += rr.z; v.w += rr.w;
                }
                *(float4*)(C + (size_t)m * J.ldc + n) = v;
            }
        } else if (J.outMode == 1) {
            __nv_bfloat16* C = (__nv_bfloat16*)J.C;
#pragma unroll
            for (int i = 0; i < 8; i++) {
                const int idx = tid + i * 256;
                const int row = idx >> 5;
                const int c4  = (idx & 31) * 4;
                float4 v = *(float4*)&stage[row * SP + c4];
                v.x *= sc; v.y *= sc; v.z *= sc; v.w *= sc;
                const int n = n0 + c4;
                if (J.bias) { v.x += J.bias[n]; v.y += J.bias[n + 1]; v.z += J.bias[n + 2]; v.w += J.bias[n + 3]; }
                uint2 o = make_uint2(pk2(v.x, v.y), pk2(v.z, v.w));
                *(uint2*)(C + (size_t)(m0 + p * 64 + row) * J.ldc + n) = o;
            }
        } else {
            __nv_bfloat16* C = (__nv_bfloat16*)J.C;
#pragma unroll
            for (int i = 0; i < 8; i++) {
                const int idx = tid + i * 256;
                const int mq  = (idx & 15) * 4;
                const int col = idx >> 4;
                const float bv = J.bias ? J.bias[n0 + col] : 0.0f;
                float f0 = stage[(mq + 0) * SP + col] * sc + bv;
                float f1 = stage[(mq + 1) * SP + col] * sc + bv;
                float f2 = stage[(mq + 2) * SP + col] * sc + bv;
                float f3 = stage[(mq + 3) * SP + col] * sc + bv;
                uint2 o = make_uint2(pk2(f0, f1), pk2(f2, f3));
                *(uint2*)(C + (size_t)(n0 + col) * J.ldc + m0 + p * 64 + mq) = o;
            }
        }
        __syncthreads();
    }
}

// ---------------------------------------------------------------------------
// fp32 -> bf16 bulk convert, 10 tensors in one launch (grid.y = tensor idx)
// ---------------------------------------------------------------------------
struct CvtJobs { const float* s[10]; __nv_bfloat16* d[10]; int n[10]; };

__global__ __launch_bounds__(256) void cvt_bf(CvtJobs j)
{
    const int t = blockIdx.y;
    const float* src = j.s[t];
    __nv_bfloat16* dst = j.d[t];
    const int n = j.n[t];
    const int stride = gridDim.x * blockDim.x * 4;
    for (int i = (blockIdx.x * blockDim.x + threadIdx.x) * 4; i < n; i += stride) {
        float4 v = *(const float4*)(src + i);
        uint2 o = make_uint2(pk2(v.x, v.y), pk2(v.z, v.w));
        *(uint2*)(dst + i) = o;
    }
}

// ---------------------------------------------------------------------------
// Row softmax (2048 cols): bf16 scaled logits in -> bf16 probs out.
// One block per row; grid.y selects direction.
// ---------------------------------------------------------------------------
__global__ __launch_bounds__(256) void softmax_bf(
    const __nv_bfloat16* __restrict__ S0, __nv_bfloat16* __restrict__ P0,
    const __nv_bfloat16* __restrict__ S1, __nv_bfloat16* __restrict__ P1)
{
    const __nv_bfloat16* S = blockIdx.y ? S1 : S0;
    __nv_bfloat16* P = blockIdx.y ? P1 : P0;
    const __nv_bfloat16* row = S + (size_t)blockIdx.x * NTOK;
    __nv_bfloat16* prow = P + (size_t)blockIdx.x * NTOK;
    const int tid = threadIdx.x;

    uint4 u = *(const uint4*)(row + tid * 8);
    float v[8];
    {
        const uint32_t w[4] = {u.x, u.y, u.z, u.w};
#pragma unroll
        for (int q = 0; q < 4; q++) {
            __nv_bfloat162 t = *reinterpret_cast<const __nv_bfloat162*>(&w[q]);
            float2 f = __bfloat1622float2(t);
            v[2 * q] = f.x; v[2 * q + 1] = f.y;
        }
    }

    float mx = -1e30f;
#pragma unroll
    for (int i = 0; i < 8; i++) mx = fmaxf(mx, v[i]);

    __shared__ float red[8];
#pragma unroll
    for (int o = 16; o; o >>= 1) mx = fmaxf(mx, __shfl_xor_sync(0xffffffffu, mx, o));
    if ((tid & 31) == 0) red[tid >> 5] = mx;
    __syncthreads();
    mx = red[0];
#pragma unroll
    for (int i = 1; i < 8; i++) mx = fmaxf(mx, red[i]);

    float sum = 0.0f;
#pragma unroll
    for (int i = 0; i < 8; i++) { v[i] = __expf(v[i] - mx); sum += v[i]; }
    __syncthreads();
#pragma unroll
    for (int o = 16; o; o >>= 1) sum += __shfl_xor_sync(0xffffffffu, sum, o);
    if ((tid & 31) == 0) red[tid >> 5] = sum;
    __syncthreads();
    sum = red[0];
#pragma unroll
    for (int i = 1; i < 8; i++) sum += red[i];

    const float inv = 1.0f / sum;
    uint4 o = make_uint4(pk2(v[0] * inv, v[1] * inv), pk2(v[2] * inv, v[3] * inv),
                         pk2(v[4] * inv, v[5] * inv), pk2(v[6] * inv, v[7] * inv));
    *(uint4*)(prow + tid * 8) = o;
}

// ---------------------------------------------------------------------------
extern "C" void kernel_launch(void* const* d_in, const int* in_sizes, int n_in,
                              void* d_out, int out_size)
{
    (void)in_sizes; (void)n_in; (void)out_size;

    const float* image = (const float*)d_in[0];
    const float* meta  = (const float*)d_in[1];
    const float* Wq_m  = (const float*)d_in[2];  const float* bq_m = (const float*)d_in[3];
    const float* Wk_i  = (const float*)d_in[4];  const float* bk_i = (const float*)d_in[5];
    const float* Wv_i  = (const float*)d_in[6];  const float* bv_i = (const float*)d_in[7];
    const float* Wq_i  = (const float*)d_in[8];  const float* bq_i = (const float*)d_in[9];
    const float* Wk_m  = (const float*)d_in[10]; const float* bk_m = (const float*)d_in[11];
    const float* Wv_m  = (const float*)d_in[12]; const float* bv_m = (const float*)d_in[13];
    const float* Wli   = (const float*)d_in[14]; const float* bli  = (const float*)d_in[15];
    const float* Wlm   = (const float*)d_in[16]; const float* blm  = (const float*)d_in[17];
    float* out = (float*)d_out;

    __nv_bfloat16 *bimg, *bmet, *wqm, *wki, *wvi, *wqi, *wkm, *wvm, *wli, *wlm;
    __nv_bfloat16 *qm, *ki, *vit, *qi, *km, *vmt, *si, *sm, *pi, *pm, *ci, *cm;
    cudaGetSymbolAddress((void**)&bimg, g_bimg);
    cudaGetSymbolAddress((void**)&bmet, g_bmet);
    cudaGetSymbolAddress((void**)&wqm,  g_wqm);
    cudaGetSymbolAddress((void**)&wki,  g_wki);
    cudaGetSymbolAddress((void**)&wvi,  g_wvi);
    cudaGetSymbolAddress((void**)&wqi,  g_wqi);
    cudaGetSymbolAddress((void**)&wkm,  g_wkm);
    cudaGetSymbolAddress((void**)&wvm,  g_wvm);
    cudaGetSymbolAddress((void**)&wli,  g_wli);
    cudaGetSymbolAddress((void**)&wlm,  g_wlm);
    cudaGetSymbolAddress((void**)&qm,   g_qm);
    cudaGetSymbolAddress((void**)&ki,   g_ki);
    cudaGetSymbolAddress((void**)&vit,  g_vit);
    cudaGetSymbolAddress((void**)&qi,   g_qi);
    cudaGetSymbolAddress((void**)&km,   g_km);
    cudaGetSymbolAddress((void**)&vmt,  g_vmt);
    cudaGetSymbolAddress((void**)&si,   g_si);
    cudaGetSymbolAddress((void**)&sm,   g_sm);
    cudaGetSymbolAddress((void**)&pi,   g_pi);
    cudaGetSymbolAddress((void**)&pm,   g_pm);
    cudaGetSymbolAddress((void**)&ci,   g_ci);
    cudaGetSymbolAddress((void**)&cm,   g_cm);

    cudaFuncSetAttribute(gemm_batch, cudaFuncAttributeMaxDynamicSharedMemorySize, SMEM_DYN);

    // ---- pre-convert all fp32 operands to bf16 (one launch)
    {
        CvtJobs j;
        const int nW = NH * DIM * DIM;
        const int nL = DIM * NH * DIM;
        const int nX = NTOK * DIM;
        j.s[0] = image; j.d[0] = bimg; j.n[0] = nX;
        j.s[1] = meta;  j.d[1] = bmet; j.n[1] = nX;
        j.s[2] = Wq_m;  j.d[2] = wqm;  j.n[2] = nW;
        j.s[3] = Wk_i;  j.d[3] = wki;  j.n[3] = nW;
        j.s[4] = Wv_i;  j.d[4] = wvi;  j.n[4] = nW;
        j.s[5] = Wq_i;  j.d[5] = wqi;  j.n[5] = nW;
        j.s[6] = Wk_m;  j.d[6] = wkm;  j.n[6] = nW;
        j.s[7] = Wv_m;  j.d[7] = wvm;  j.n[7] = nW;
        j.s[8] = Wli;   j.d[8] = wli;  j.n[8] = nL;
        j.s[9] = Wlm;   j.d[9] = wlm;  j.n[9] = nL;
        cvt_bf<<<dim3(1024, 10), 256>>>(j);
    }

    const dim3 blk(256);
    const size_t sW  = (size_t)DIM * DIM;
    const size_t sO  = (size_t)NTOK * DIM;
    const size_t sOT = (size_t)DIM * NTOK;
    const size_t sS  = (size_t)NTOK * NTOK;
    const float scale = 0.04419417382415922f;   // 1/sqrt(512)

    // ---- projections: ONE launch, 48 jobs (6 gemms x 8 heads)
    {
        Jobs jb;
        const __nv_bfloat16* As[6]  = {bmet, bimg, bimg, bimg, bmet, bmet};
        const __nv_bfloat16* Ws[6]  = {wqm,  wki,  wvi,  wqi,  wkm,  wvm};
        __nv_bfloat16*       Cs[6]  = {qm,   ki,   vit,  qi,   km,   vmt};
        const float*         Bs[6]  = {bq_m, bk_i, bv_i, bq_i, bk_m, bv_m};
        const int            md[6]  = {1, 1, 2, 1, 1, 2};
        for (int g = 0; g < 6; g++)
            for (int h = 0; h < NH; h++) {
                Job& J = jb.j[g * NH + h];
                J.A = As[g];
                J.B = Ws[g] + (size_t)h * sW;
                J.C = (char*)(Cs[g] + (md[g] == 2 ? (size_t)h * sOT : (size_t)h * sO));
                J.bias = Bs[g] + (size_t)h * DIM;
                J.resid = nullptr;
                J.scale = 1.0f;
                J.lda = DIM; J.ldb = DIM;
                J.ldc = (md[g] == 2) ? NTOK : DIM;
                J.ldr = 0; J.outMode = md[g];
            }
        gemm_batch<<<dim3(DIM / 128, NTOK / 128, 48), blk, SMEM_DYN>>>(jb, DIM);
    }

    // ---- scores: ONE launch, 16 jobs, bf16 pre-scaled logits out
    {
        Jobs jb;
        for (int p = 0; p < 2; p++)
            for (int h = 0; h < NH; h++) {
                Job& J = jb.j[p * NH + h];
                J.A = (p ? qi : qm) + (size_t)h * sO;
                J.B = (p ? km : ki) + (size_t)h * sO;
                J.C = (char*)((p ? sm : si) + (size_t)h * sS);
                J.bias = nullptr; J.resid = nullptr;
                J.scale = scale;
                J.lda = DIM; J.ldb = DIM; J.ldc = NTOK; J.ldr = 0; J.outMode = 1;
            }
        gemm_batch<<<dim3(NTOK / 128, NTOK / 128, 16), blk, SMEM_DYN>>>(jb, DIM);
    }

    // ---- softmax (both directions, one launch), bf16 in/out
    softmax_bf<<<dim3(NH * NTOK, 2), 256>>>(si, pi, sm, pm);

    // ---- AV: ONE launch, 16 jobs -> concat [2048, 4096] bf16
    {
        Jobs jb;
        for (int p = 0; p < 2; p++)
            for (int h = 0; h < NH; h++) {
                Job& J = jb.j[p * NH + h];
                J.A = (p ? pm : pi) + (size_t)h * sS;
                J.B = (p ? vmt : vit) + (size_t)h * sOT;
                J.C = (char*)((p ? cm : ci) + (size_t)h * DIM);
                J.bias = nullptr; J.resid = nullptr;
                J.scale = 1.0f;
                J.lda = NTOK; J.ldb = NTOK; J.ldc = NH * DIM; J.ldr = 0; J.outMode = 1;
            }
        gemm_batch<<<dim3(DIM / 128, NTOK / 128, 16), blk, SMEM_DYN>>>(jb, NTOK);
    }

    // ---- final linears: ONE launch, 2 jobs, bias + fp32 residual -> d_out
    {
        Jobs jb;
        jb.j[0] = { ci, wli, (char*)out,          bli, image, 1.0f, NH * DIM, NH * DIM, 2 * DIM, DIM, 0 };
        jb.j[1] = { cm, wlm, (char*)(out + DIM),  blm, meta,  1.0f, NH * DIM, NH * DIM, 2 * DIM, DIM, 0 };
        gemm_batch<<<dim3(DIM / 128, NTOK / 128, 2), blk, SMEM_DYN>>>(jb, NH * DIM);
    }
}

// round 13
// speedup vs baseline: 1.4536x; 1.1353x over previous
#include <cuda_runtime.h>
#include <cuda_bf16.h>
#include <cstdint>

static constexpr int NTOK = 2048;
static constexpr int DIM  = 512;
static constexpr int NH   = 8;

// fp8 P-scaling: probs (~5e-4) sit below e4m3 subnormal min (1.95e-3) — R12 failure.
// Store P*1024 in fp8, divide by 1024 in the AV epilogue (exact power of 2).
static constexpr float PSCALE     = 1024.0f;
static constexpr float PSCALE_INV = 1.0f / 1024.0f;

// ---------------- scratch (allocation-free: __device__ globals) ----------------
__device__ __align__(128) __nv_bfloat16 g_bimg[(size_t)NTOK * DIM];
__device__ __align__(128) __nv_bfloat16 g_bmet[(size_t)NTOK * DIM];
__device__ __align__(128) __nv_bfloat16 g_wqm [(size_t)NH * DIM * DIM];
__device__ __align__(128) __nv_bfloat16 g_wki [(size_t)NH * DIM * DIM];
__device__ __align__(128) __nv_bfloat16 g_wvi [(size_t)NH * DIM * DIM];
__device__ __align__(128) __nv_bfloat16 g_wqi [(size_t)NH * DIM * DIM];
__device__ __align__(128) __nv_bfloat16 g_wkm [(size_t)NH * DIM * DIM];
__device__ __align__(128) __nv_bfloat16 g_wvm [(size_t)NH * DIM * DIM];
__device__ __align__(128) __nv_bfloat16 g_wli [(size_t)DIM * NH * DIM];
__device__ __align__(128) __nv_bfloat16 g_wlm [(size_t)DIM * NH * DIM];
__device__ __align__(128) uint8_t       g_qm  [(size_t)NH * NTOK * DIM];      // Q fp8
__device__ __align__(128) uint8_t       g_ki  [(size_t)NH * NTOK * DIM];      // K fp8
__device__ __align__(128) uint8_t       g_vit [(size_t)NH * DIM * NTOK];      // V_i^T fp8
__device__ __align__(128) uint8_t       g_qi  [(size_t)NH * NTOK * DIM];
__device__ __align__(128) uint8_t       g_km  [(size_t)NH * NTOK * DIM];
__device__ __align__(128) uint8_t       g_vmt [(size_t)NH * DIM * NTOK];
__device__ __align__(128) __nv_bfloat16 g_si  [(size_t)NH * NTOK * NTOK];     // scaled logits bf16
__device__ __align__(128) __nv_bfloat16 g_sm  [(size_t)NH * NTOK * NTOK];
__device__ __align__(128) uint8_t       g_pi  [(size_t)NH * NTOK * NTOK];     // probs*1024 fp8
__device__ __align__(128) uint8_t       g_pm  [(size_t)NH * NTOK * NTOK];
__device__ __align__(128) __nv_bfloat16 g_ci  [(size_t)NTOK * NH * DIM];
__device__ __align__(128) __nv_bfloat16 g_cm  [(size_t)NTOK * NH * DIM];

#define DEVINL __device__ __forceinline__

DEVINL uint32_t s2u(const void* p) { return (uint32_t)__cvta_generic_to_shared(p); }

DEVINL void ldsm4(uint32_t* r, uint32_t a) {
    asm volatile("ldmatrix.sync.aligned.m8n8.x4.shared.b16 {%0,%1,%2,%3}, [%4];"
        : "=r"(r[0]), "=r"(r[1]), "=r"(r[2]), "=r"(r[3]) : "r"(a));
}
DEVINL void mma16(float* c, const uint32_t* a, uint32_t b0, uint32_t b1) {
    asm volatile("mma.sync.aligned.m16n8k16.row.col.f32.bf16.bf16.f32 "
        "{%0,%1,%2,%3},{%4,%5,%6,%7},{%8,%9},{%0,%1,%2,%3};"
        : "+f"(c[0]), "+f"(c[1]), "+f"(c[2]), "+f"(c[3])
        : "r"(a[0]), "r"(a[1]), "r"(a[2]), "r"(a[3]), "r"(b0), "r"(b1));
}
DEVINL void mma32f8(float* c, const uint32_t* a, uint32_t b0, uint32_t b1) {
    asm volatile("mma.sync.aligned.m16n8k32.row.col.f32.e4m3.e4m3.f32 "
        "{%0,%1,%2,%3},{%4,%5,%6,%7},{%8,%9},{%0,%1,%2,%3};"
        : "+f"(c[0]), "+f"(c[1]), "+f"(c[2]), "+f"(c[3])
        : "r"(a[0]), "r"(a[1]), "r"(a[2]), "r"(a[3]), "r"(b0), "r"(b1));
}
DEVINL uint32_t pk2(float lo, float hi) {
    __nv_bfloat162 t = __floats2bfloat162_rn(lo, hi);
    return *reinterpret_cast<uint32_t*>(&t);
}
// pack 4 floats -> 4 e4m3 bytes (little-endian order v0..v3)
DEVINL uint32_t pk4f8(float v0, float v1, float v2, float v3) {
    uint16_t lo, hi;
    asm("cvt.rn.satfinite.e4m3x2.f32 %0, %1, %2;" : "=h"(lo) : "f"(v1), "f"(v0));
    asm("cvt.rn.satfinite.e4m3x2.f32 %0, %1, %2;" : "=h"(hi) : "f"(v3), "f"(v2));
    return (uint32_t)lo | ((uint32_t)hi << 16);
}
DEVINL void cp16(uint32_t dst, const void* src) {
    asm volatile("cp.async.cg.shared.global [%0], [%1], 16;" :: "r"(dst), "l"(src));
}
#define CP_COMMIT() asm volatile("cp.async.commit_group;")
#define CP_WAIT(n)  asm volatile("cp.async.wait_group %0;" :: "n"(n))

static constexpr int RPB  = 80;   // smem tile row pitch bytes: 64 data + 16 pad
static constexpr int SP   = 132;  // epilogue stage pitch (floats) — mult of 4 (R5 lesson)
static constexpr int NS   = 4;    // cp.async pipeline stages
static constexpr int TILE_B  = 128 * RPB;            // 10240 B per tile
static constexpr int STAGE_B = 2 * TILE_B;           // A+B per stage
static constexpr int SMEM_DYN = NS * STAGE_B;        // 81920 B

// --------------- per-z job descriptor (all pointers pre-offset on host) --------
// outMode: 0 fp32, 1 bf16, 2 bf16 transposed, 3 fp8, 4 fp8 transposed
struct Job {
    const char* A;
    const char* B;
    char*       C;
    const float* bias;
    const float* resid;
    float scale;
    int lda, ldb, ldc, ldr, outMode;   // lda/ldb/ldc in ELEMENTS of their dtype
};
static constexpr int MAXJ = 48;
struct Jobs { Job j[MAXJ]; };

// ---------------------------------------------------------------------------
// mma GEMM (NT), batched by z over a job table.
// F8=0: bf16 operands, K-chunk 32 elems; F8=1: e4m3 operands, K-chunk 64 elems.
// Identical 64B/row/chunk byte geometry either way (fp8 k32 frag == bf16 k16 frag).
// CTA 128x128, 256 thr, warp tile 64x32, 4-stage cp.async.
// ---------------------------------------------------------------------------
template <int F8>
__global__ __launch_bounds__(256, 2) void gemm_batch(Jobs jobs, int K)
{
    extern __shared__ __align__(128) char dsm[];
    const uint32_t sbase = s2u(dsm);
    const Job J = jobs.j[blockIdx.z];
    const int esz = F8 ? 1 : 2;

    const int tid  = threadIdx.x;
    const int warp = tid >> 5, lane = tid & 31;
    const int wm = warp & 1, wn = warp >> 1;
    const int gid = lane >> 2, tig = lane & 3;
    const int m0 = blockIdx.y * 128, n0 = blockIdx.x * 128;

    const int frow = tid & 127;
    const int fup  = (tid >> 7) * 2;          // 16B units {fup, fup+1} of the 64B row-chunk
    const char* Ap = J.A + (size_t)(m0 + frow) * J.lda * esz + fup * 16;
    const char* Bp = J.B + (size_t)(n0 + frow) * J.ldb * esz + fup * 16;
    const uint32_t sa_t = sbase + frow * RPB + fup * 16;
    const uint32_t sb_t = sa_t + TILE_B;

    const int NC = K / (F8 ? 64 : 32);

    auto issue = [&](int c) {
        const uint32_t so = (uint32_t)((c & (NS - 1)) * STAGE_B);
        const char* ga = Ap + (size_t)c * 64;
        const char* gb = Bp + (size_t)c * 64;
        cp16(sa_t + so,      ga);
        cp16(sa_t + so + 16, ga + 16);
        cp16(sb_t + so,      gb);
        cp16(sb_t + so + 16, gb + 16);
    };

    float acc[4][4][4];
#pragma unroll
    for (int i = 0; i < 4; i++)
#pragma unroll
        for (int j = 0; j < 4; j++)
#pragma unroll
            for (int r = 0; r < 4; r++) acc[i][j][r] = 0.0f;

    const int lrow8  = (lane & 7) + ((lane >> 3) & 1) * 8;
    const int lchunk = (lane >> 4) * 16;
    uint32_t aoff[4], boff[2];
#pragma unroll
    for (int mt = 0; mt < 4; mt++) aoff[mt] = (uint32_t)((wm * 64 + mt * 16 + lrow8) * RPB + lchunk);
#pragma unroll
    for (int np = 0; np < 2; np++) boff[np] = (uint32_t)((wn * 32 + np * 16 + lrow8) * RPB + lchunk);

#pragma unroll
    for (int c = 0; c < NS - 1; c++) {
        if (c < NC) issue(c);
        CP_COMMIT();
    }

    for (int c = 0; c < NC; c++) {
        CP_WAIT(NS - 2);
        __syncthreads();
        if (c + NS - 1 < NC) issue(c + NS - 1);
        CP_COMMIT();

        const uint32_t so = (uint32_t)((c & (NS - 1)) * STAGE_B);
        const uint32_t ab = sbase + so;
        const uint32_t bb = ab + TILE_B;
#pragma unroll
        for (int ks = 0; ks < 2; ks++) {
            uint32_t a[4][4], b[2][4];
#pragma unroll
            for (int mt = 0; mt < 4; mt++) ldsm4(a[mt], ab + aoff[mt] + ks * 32);
#pragma unroll
            for (int np = 0; np < 2; np++) ldsm4(b[np], bb + boff[np] + ks * 32);
#pragma unroll
            for (int mt = 0; mt < 4; mt++)
#pragma unroll
                for (int np = 0; np < 2; np++) {
                    if (F8) {
                        mma32f8(acc[mt][2 * np],     a[mt], b[np][0], b[np][2]);
                        mma32f8(acc[mt][2 * np + 1], a[mt], b[np][1], b[np][3]);
                    } else {
                        mma16(acc[mt][2 * np],     a[mt], b[np][0], b[np][2]);
                        mma16(acc[mt][2 * np + 1], a[mt], b[np][1], b[np][3]);
                    }
                }
        }
    }
    CP_WAIT(0);
    __syncthreads();

    // -------- epilogue: stage 64 m-rows at a time through smem --------
    float* stage = (float*)dsm;
    const float sc = J.scale;
    for (int p = 0; p < 2; p++) {
        if (wm == p) {
#pragma unroll
            for (int mt = 0; mt < 4; mt++) {
                const int lr = mt * 16 + gid;
#pragma unroll
                for (int nt = 0; nt < 4; nt++) {
                    const int col = wn * 32 + nt * 8 + 2 * tig;
                    *(float2*)&stage[lr * SP + col]       = make_float2(acc[mt][nt][0], acc[mt][nt][1]);
                    *(float2*)&stage[(lr + 8) * SP + col] = make_float2(acc[mt][nt][2], acc[mt][nt][3]);
                }
            }
        }
        __syncthreads();

        if (J.outMode == 0) {
            float* C = (float*)J.C;
#pragma unroll
            for (int i = 0; i < 8; i++) {
                const int idx = tid + i * 256;
                const int row = idx >> 5;
                const int c4  = (idx & 31) * 4;
                float4 v = *(float4*)&stage[row * SP + c4];
                v.x *= sc; v.y *= sc; v.z *= sc; v.w *= sc;
                const int n = n0 + c4;
                if (J.bias) { v.x += J.bias[n]; v.y += J.bias[n + 1]; v.z += J.bias[n + 2]; v.w += J.bias[n + 3]; }
                const int m = m0 + p * 64 + row;
                if (J.resid) {
                    float4 rr = *(const float4*)(J.resid + (size_t)m * J.ldr + n);
                    v.x += rr.x; v.y += rr.y; v.z += rr.z; v.w += rr.w;
                }
                *(float4*)(C + (size_t)m * J.ldc + n) = v;
            }
        } else if (J.outMode == 1) {
            __nv_bfloat16* C = (__nv_bfloat16*)J.C;
#pragma unroll
            for (int i = 0; i < 8; i++) {
                const int idx = tid + i * 256;
                const int row = idx >> 5;
                const int c4  = (idx & 31) * 4;
                float4 v = *(float4*)&stage[row * SP + c4];
                v.x *= sc; v.y *= sc; v.z *= sc; v.w *= sc;
                const int n = n0 + c4;
                if (J.bias) { v.x += J.bias[n]; v.y += J.bias[n + 1]; v.z += J.bias[n + 2]; v.w += J.bias[n + 3]; }
                uint2 o = make_uint2(pk2(v.x, v.y), pk2(v.z, v.w));
                *(uint2*)(C + (size_t)(m0 + p * 64 + row) * J.ldc + n) = o;
            }
        } else if (J.outMode == 2) {
            __nv_bfloat16* C = (__nv_bfloat16*)J.C;
#pragma unroll
            for (int i = 0; i < 8; i++) {
                const int idx = tid + i * 256;
                const int mq  = (idx & 15) * 4;
                const int col = idx >> 4;
                const float bv = J.bias ? J.bias[n0 + col] : 0.0f;
                float f0 = stage[(mq + 0) * SP + col] * sc + bv;
                float f1 = stage[(mq + 1) * SP + col] * sc + bv;
                float f2 = stage[(mq + 2) * SP + col] * sc + bv;
                float f3 = stage[(mq + 3) * SP + col] * sc + bv;
                uint2 o = make_uint2(pk2(f0, f1), pk2(f2, f3));
                *(uint2*)(C + (size_t)(n0 + col) * J.ldc + m0 + p * 64 + mq) = o;
            }
        } else if (J.outMode == 3) {
            uint8_t* C = (uint8_t*)J.C;
#pragma unroll
            for (int i = 0; i < 8; i++) {
                const int idx = tid + i * 256;
                const int row = idx >> 5;
                const int c4  = (idx & 31) * 4;
                float4 v = *(float4*)&stage[row * SP + c4];
                v.x *= sc; v.y *= sc; v.z *= sc; v.w *= sc;
                const int n = n0 + c4;
                if (J.bias) { v.x += J.bias[n]; v.y += J.bias[n + 1]; v.z += J.bias[n + 2]; v.w += J.bias[n + 3]; }
                *(uint32_t*)(C + (size_t)(m0 + p * 64 + row) * J.ldc + n) = pk4f8(v.x, v.y, v.z, v.w);
            }
        } else {
            uint8_t* C = (uint8_t*)J.C;
#pragma unroll
            for (int i = 0; i < 8; i++) {
                const int idx = tid + i * 256;
                const int mq  = (idx & 15) * 4;
                const int col = idx >> 4;
                const float bv = J.bias ? J.bias[n0 + col] : 0.0f;
                float f0 = stage[(mq + 0) * SP + col] * sc + bv;
                float f1 = stage[(mq + 1) * SP + col] * sc + bv;
                float f2 = stage[(mq + 2) * SP + col] * sc + bv;
                float f3 = stage[(mq + 3) * SP + col] * sc + bv;
                *(uint32_t*)(C + (size_t)(n0 + col) * J.ldc + m0 + p * 64 + mq) = pk4f8(f0, f1, f2, f3);
            }
        }
        __syncthreads();
    }
}

// ---------------------------------------------------------------------------
// fp32 -> bf16 bulk convert, 10 tensors in one launch (grid.y = tensor idx)
// ---------------------------------------------------------------------------
struct CvtJobs { const float* s[10]; __nv_bfloat16* d[10]; int n[10]; };

__global__ __launch_bounds__(256) void cvt_bf(CvtJobs j)
{
    const int t = blockIdx.y;
    const float* src = j.s[t];
    __nv_bfloat16* dst = j.d[t];
    const int n = j.n[t];
    const int stride = gridDim.x * blockDim.x * 4;
    for (int i = (blockIdx.x * blockDim.x + threadIdx.x) * 4; i < n; i += stride) {
        float4 v = *(const float4*)(src + i);
        uint2 o = make_uint2(pk2(v.x, v.y), pk2(v.z, v.w));
        *(uint2*)(dst + i) = o;
    }
}

// ---------------------------------------------------------------------------
// Row softmax (2048 cols): bf16 scaled logits in -> fp8 e4m3 probs*PSCALE out.
// ---------------------------------------------------------------------------
__global__ __launch_bounds__(256) void softmax_bf(
    const __nv_bfloat16* __restrict__ S0, uint8_t* __restrict__ P0,
    const __nv_bfloat16* __restrict__ S1, uint8_t* __restrict__ P1)
{
    const __nv_bfloat16* S = blockIdx.y ? S1 : S0;
    uint8_t* P = blockIdx.y ? P1 : P0;
    const __nv_bfloat16* row = S + (size_t)blockIdx.x * NTOK;
    uint8_t* prow = P + (size_t)blockIdx.x * NTOK;
    const int tid = threadIdx.x;

    uint4 u = *(const uint4*)(row + tid * 8);
    float v[8];
    {
        const uint32_t w[4] = {u.x, u.y, u.z, u.w};
#pragma unroll
        for (int q = 0; q < 4; q++) {
            __nv_bfloat162 t = *reinterpret_cast<const __nv_bfloat162*>(&w[q]);
            float2 f = __bfloat1622float2(t);
            v[2 * q] = f.x; v[2 * q + 1] = f.y;
        }
    }

    float mx = -1e30f;
#pragma unroll
    for (int i = 0; i < 8; i++) mx = fmaxf(mx, v[i]);

    __shared__ float red[8];
#pragma unroll
    for (int o = 16; o; o >>= 1) mx = fmaxf(mx, __shfl_xor_sync(0xffffffffu, mx, o));
    if ((tid & 31) == 0) red[tid >> 5] = mx;
    __syncthreads();
    mx = red[0];
#pragma unroll
    for (int i = 1; i < 8; i++) mx = fmaxf(mx, red[i]);

    float sum = 0.0f;
#pragma unroll
    for (int i = 0; i < 8; i++) { v[i] = __expf(v[i] - mx); sum += v[i]; }
    __syncthreads();
#pragma unroll
    for (int o = 16; o; o >>= 1) sum += __shfl_xor_sync(0xffffffffu, sum, o);
    if ((tid & 31) == 0) red[tid >> 5] = sum;
    __syncthreads();
    sum = red[0];
#pragma unroll
    for (int i = 1; i < 8; i++) sum += red[i];

    const float inv = PSCALE / sum;   // fold fp8 range-scaling into normalization
    uint32_t o0 = pk4f8(v[0] * inv, v[1] * inv, v[2] * inv, v[3] * inv);
    uint32_t o1 = pk4f8(v[4] * inv, v[5] * inv, v[6] * inv, v[7] * inv);
    *(uint2*)(prow + tid * 8) = make_uint2(o0, o1);
}

// ---------------------------------------------------------------------------
extern "C" void kernel_launch(void* const* d_in, const int* in_sizes, int n_in,
                              void* d_out, int out_size)
{
    (void)in_sizes; (void)n_in; (void)out_size;

    const float* image = (const float*)d_in[0];
    const float* meta  = (const float*)d_in[1];
    const float* Wq_m  = (const float*)d_in[2];  const float* bq_m = (const float*)d_in[3];
    const float* Wk_i  = (const float*)d_in[4];  const float* bk_i = (const float*)d_in[5];
    const float* Wv_i  = (const float*)d_in[6];  const float* bv_i = (const float*)d_in[7];
    const float* Wq_i  = (const float*)d_in[8];  const float* bq_i = (const float*)d_in[9];
    const float* Wk_m  = (const float*)d_in[10]; const float* bk_m = (const float*)d_in[11];
    const float* Wv_m  = (const float*)d_in[12]; const float* bv_m = (const float*)d_in[13];
    const float* Wli   = (const float*)d_in[14]; const float* bli  = (const float*)d_in[15];
    const float* Wlm   = (const float*)d_in[16]; const float* blm  = (const float*)d_in[17];
    float* out = (float*)d_out;

    __nv_bfloat16 *bimg, *bmet, *wqm, *wki, *wvi, *wqi, *wkm, *wvm, *wli, *wlm;
    __nv_bfloat16 *si, *sm, *ci, *cm;
    uint8_t *qm, *ki, *vit, *qi, *km, *vmt, *pi, *pm;
    cudaGetSymbolAddress((void**)&bimg, g_bimg);
    cudaGetSymbolAddress((void**)&bmet, g_bmet);
    cudaGetSymbolAddress((void**)&wqm,  g_wqm);
    cudaGetSymbolAddress((void**)&wki,  g_wki);
    cudaGetSymbolAddress((void**)&wvi,  g_wvi);
    cudaGetSymbolAddress((void**)&wqi,  g_wqi);
    cudaGetSymbolAddress((void**)&wkm,  g_wkm);
    cudaGetSymbolAddress((void**)&wvm,  g_wvm);
    cudaGetSymbolAddress((void**)&wli,  g_wli);
    cudaGetSymbolAddress((void**)&wlm,  g_wlm);
    cudaGetSymbolAddress((void**)&qm,   g_qm);
    cudaGetSymbolAddress((void**)&ki,   g_ki);
    cudaGetSymbolAddress((void**)&vit,  g_vit);
    cudaGetSymbolAddress((void**)&qi,   g_qi);
    cudaGetSymbolAddress((void**)&km,   g_km);
    cudaGetSymbolAddress((void**)&vmt,  g_vmt);
    cudaGetSymbolAddress((void**)&si,   g_si);
    cudaGetSymbolAddress((void**)&sm,   g_sm);
    cudaGetSymbolAddress((void**)&pi,   g_pi);
    cudaGetSymbolAddress((void**)&pm,   g_pm);
    cudaGetSymbolAddress((void**)&ci,   g_ci);
    cudaGetSymbolAddress((void**)&cm,   g_cm);

    cudaFuncSetAttribute(gemm_batch<0>, cudaFuncAttributeMaxDynamicSharedMemorySize, SMEM_DYN);
    cudaFuncSetAttribute(gemm_batch<1>, cudaFuncAttributeMaxDynamicSharedMemorySize, SMEM_DYN);

    // ---- pre-convert all fp32 operands to bf16 (one launch)
    {
        CvtJobs j;
        const int nW = NH * DIM * DIM;
        const int nL = DIM * NH * DIM;
        const int nX = NTOK * DIM;
        j.s[0] = image; j.d[0] = bimg; j.n[0] = nX;
        j.s[1] = meta;  j.d[1] = bmet; j.n[1] = nX;
        j.s[2] = Wq_m;  j.d[2] = wqm;  j.n[2] = nW;
        j.s[3] = Wk_i;  j.d[3] = wki;  j.n[3] = nW;
        j.s[4] = Wv_i;  j.d[4] = wvi;  j.n[4] = nW;
        j.s[5] = Wq_i;  j.d[5] = wqi;  j.n[5] = nW;
        j.s[6] = Wk_m;  j.d[6] = wkm;  j.n[6] = nW;
        j.s[7] = Wv_m;  j.d[7] = wvm;  j.n[7] = nW;
        j.s[8] = Wli;   j.d[8] = wli;  j.n[8] = nL;
        j.s[9] = Wlm;   j.d[9] = wlm;  j.n[9] = nL;
        cvt_bf<<<dim3(1024, 10), 256>>>(j);
    }

    const dim3 blk(256);
    const size_t sW  = (size_t)DIM * DIM;
    const size_t sO  = (size_t)NTOK * DIM;
    const size_t sOT = (size_t)DIM * NTOK;
    const size_t sS  = (size_t)NTOK * NTOK;
    const float scale = 0.04419417382415922f;   // 1/sqrt(512)

    // ---- projections (bf16 in): ONE launch, 48 jobs; Q/K -> fp8, V -> fp8^T
    {
        Jobs jb;
        const __nv_bfloat16* As[6]  = {bmet, bimg, bimg, bimg, bmet, bmet};
        const __nv_bfloat16* Ws[6]  = {wqm,  wki,  wvi,  wqi,  wkm,  wvm};
        uint8_t*             Cs[6]  = {qm,   ki,   vit,  qi,   km,   vmt};
        const float*         Bs[6]  = {bq_m, bk_i, bv_i, bq_i, bk_m, bv_m};
        const int            md[6]  = {3, 3, 4, 3, 3, 4};
        for (int g = 0; g < 6; g++)
            for (int h = 0; h < NH; h++) {
                Job& J = jb.j[g * NH + h];
                J.A = (const char*)As[g];
                J.B = (const char*)(Ws[g] + (size_t)h * sW);
                J.C = (char*)(Cs[g] + (md[g] == 4 ? (size_t)h * sOT : (size_t)h * sO));
                J.bias = Bs[g] + (size_t)h * DIM;
                J.resid = nullptr;
                J.scale = 1.0f;
                J.lda = DIM; J.ldb = DIM;
                J.ldc = (md[g] == 4) ? NTOK : DIM;
                J.ldr = 0; J.outMode = md[g];
            }
        gemm_batch<0><<<dim3(DIM / 128, NTOK / 128, 48), blk, SMEM_DYN>>>(jb, DIM);
    }

    // ---- scores (fp8 in): ONE launch, 16 jobs, bf16 pre-scaled logits out
    {
        Jobs jb;
        for (int p = 0; p < 2; p++)
            for (int h = 0; h < NH; h++) {
                Job& J = jb.j[p * NH + h];
                J.A = (const char*)((p ? qi : qm) + (size_t)h * sO);
                J.B = (const char*)((p ? km : ki) + (size_t)h * sO);
                J.C = (char*)((p ? sm : si) + (size_t)h * sS);
                J.bias = nullptr; J.resid = nullptr;
                J.scale = scale;
                J.lda = DIM; J.ldb = DIM; J.ldc = NTOK; J.ldr = 0; J.outMode = 1;
            }
        gemm_batch<1><<<dim3(NTOK / 128, NTOK / 128, 16), blk, SMEM_DYN>>>(jb, DIM);
    }

    // ---- softmax (both directions): bf16 logits -> fp8 probs*PSCALE
    softmax_bf<<<dim3(NH * NTOK, 2), 256>>>(si, pi, sm, pm);

    // ---- AV (fp8 in): ONE launch, 16 jobs -> concat [2048, 4096] bf16, /PSCALE
    {
        Jobs jb;
        for (int p = 0; p < 2; p++)
            for (int h = 0; h < NH; h++) {
                Job& J = jb.j[p * NH + h];
                J.A = (const char*)((p ? pm : pi) + (size_t)h * sS);
                J.B = (const char*)((p ? vmt : vit) + (size_t)h * sOT);
                J.C = (char*)((p ? cm : ci) + (size_t)h * DIM);
                J.bias = nullptr; J.resid = nullptr;
                J.scale = PSCALE_INV;
                J.lda = NTOK; J.ldb = NTOK; J.ldc = NH * DIM; J.ldr = 0; J.outMode = 1;
            }
        gemm_batch<1><<<dim3(DIM / 128, NTOK / 128, 16), blk, SMEM_DYN>>>(jb, NTOK);
    }

    // ---- final linears (bf16 in): ONE launch, 2 jobs, bias + fp32 residual -> d_out
    {
        Jobs jb;
        jb.j[0] = { (const char*)ci, (const char*)wli, (char*)out,
                    bli, image, 1.0f, NH * DIM, NH * DIM, 2 * DIM, DIM, 0 };
        jb.j[1] = { (const char*)cm, (const char*)wlm, (char*)(out + DIM),
                    blm, meta,  1.0f, NH * DIM, NH * DIM, 2 * DIM, DIM, 0 };
        gemm_batch<0><<<dim3(DIM / 128, NTOK / 128, 2), blk, SMEM_DYN>>>(jb, NH * DIM);
    }
}